// round 11
// baseline (speedup 1.0000x reference)
#include <cuda_runtime.h>
#include <math.h>

// Problem constants
#define RES_ 14
#define N_ 196
#define B_ 128
#define DIM_ 256
#define H_ 8
#define KD_ 32
#define DV_ 128
#define DH_ 1024
#define NOFF_ 196
#define QKV_ 1536
#define SCALE_ 0.17677669529663687f

typedef unsigned long long ull;

// ---- packed fp32x2 helpers -------------------------------------------------
__device__ __forceinline__ ull ffma2(ull a, ull b, ull c) {
    ull d; asm("fma.rn.f32x2 %0, %1, %2, %3;" : "=l"(d) : "l"(a), "l"(b), "l"(c)); return d;
}
__device__ __forceinline__ ull fadd2(ull a, ull b) {
    ull d; asm("add.rn.f32x2 %0, %1, %2;" : "=l"(d) : "l"(a), "l"(b)); return d;
}
__device__ __forceinline__ ull fmul2(ull a, ull b) {
    ull d; asm("mul.rn.f32x2 %0, %1, %2;" : "=l"(d) : "l"(a), "l"(b)); return d;
}
__device__ __forceinline__ ull pack2(float lo, float hi) {
    ull d; asm("mov.b64 %0, {%1, %2};" : "=l"(d) : "f"(lo), "f"(hi)); return d;
}
__device__ __forceinline__ float2 unpack2(ull d) {
    float2 r; asm("mov.b64 {%0, %1}, %2;" : "=f"(r.x), "=f"(r.y) : "l"(d)); return r;
}

// ---------------- scratch (static device globals) --------------------------
__device__ __align__(16) float g_wall[DIM_*QKV_];
__device__ __align__(16) float g_ball[QKV_];
__device__ __align__(16) float g_wp[DH_*DIM_];
__device__ __align__(16) float g_bp[DIM_];
__device__ __align__(16) float g_abm[H_*NOFF_];
__device__ __align__(16) float g_q [B_*N_*256];     // (b,n,c)
// K paired layout: g_k[((b*128 + cp)*196 + m)*2 + par], cp=c/2, par=c&1
__device__ __align__(16) float g_k [B_*256*N_];
__device__ __align__(16) float g_v [B_*N_*DH_];     // (b,n,c) — for dwconv
// V interleaved: g_v2[((b*98+pm)*1024 + c0)*2 + {0..3}] = (c0_e, c0_o, c1_e, c1_o)
__device__ __align__(16) float g_v2[B_*N_*DH_];
__device__ __align__(16) float g_vl[B_*N_*DH_];
__device__ __align__(16) float g_ao[B_*N_*DH_];     // gelu(attn_out + vl)

// ---------------- kernel 0: fold scales / mix biases ------------------------
__global__ void precompute_kernel(
    const float* __restrict__ wq, const float* __restrict__ bq,
    const float* __restrict__ sq, const float* __restrict__ tq,
    const float* __restrict__ wk, const float* __restrict__ bk,
    const float* __restrict__ sk, const float* __restrict__ tk,
    const float* __restrict__ wv, const float* __restrict__ bv,
    const float* __restrict__ sv, const float* __restrict__ tv,
    const float* __restrict__ wp, const float* __restrict__ bp,
    const float* __restrict__ sp, const float* __restrict__ tp,
    const float* __restrict__ th1, const float* __restrict__ ab)
{
    int i = blockIdx.x * blockDim.x + threadIdx.x;
    if (i < DIM_*QKV_) {
        int c = i / QKV_, o = i % QKV_;
        float w;
        if (o < 256)       w = wq[c*256 + o]        * sq[o];
        else if (o < 512)  w = wk[c*256 + (o-256)]  * sk[o-256];
        else               w = wv[c*1024 + (o-512)] * sv[o-512];
        g_wall[i] = w;
        return;
    }
    int j = i - DIM_*QKV_;
    if (j < DH_*DIM_) {
        int c = j / 256, o = j % 256;
        g_wp[j] = wp[c*256 + o] * sp[o];
        return;
    }
    int l = j - DH_*DIM_;
    if (l < QKV_) {
        float v;
        if (l < 256)       v = bq[l]*sq[l] + tq[l];
        else if (l < 512)  v = bk[l-256]*sk[l-256] + tk[l-256];
        else               v = bv[l-512]*sv[l-512] + tv[l-512];
        g_ball[l] = v;
        return;
    }
    int m2 = l - QKV_;
    if (m2 < 256) { g_bp[m2] = bp[m2]*sp[m2] + tp[m2]; return; }
    int a = m2 - 256;
    if (a < H_*NOFF_) {
        int g = a / NOFF_, f = a % NOFF_;
        float s = 0.f;
        #pragma unroll
        for (int h = 0; h < 8; h++) s = fmaf(th1[g*8+h], ab[h*NOFF_ + f], s);
        g_abm[a] = s;
    }
}

// ---------------- kernel 1: fused QKV projection GEMM (64x128 tile) --------
// W operand pre-duplicated in smem as (w,w) pairs -> zero pack MOVs in loop.
__global__ __launch_bounds__(256, 2) void proj_kernel(const float* __restrict__ hs)
{
    __shared__ __align__(16) float Xs[32][64];
    __shared__ __align__(16) ull   Ws2[32][128];
    const int tid = threadIdx.x;
    const int tx = tid & 31, ty = tid >> 5;
    const int rowBase = blockIdx.x * 64;
    const int bo = blockIdx.y * 128;

    int xbase[8];
    #pragma unroll
    for (int i = 0; i < 8; i++) {
        int idx = tid + i*256;
        int kk = idx >> 6, r = idx & 63;
        int row = rowBase + r;
        int b = row / 196, n = row - b*196;
        xbase[i] = b*50176 + kk*196 + n;
    }

    ull acc[4][4];
    #pragma unroll
    for (int i = 0; i < 4; i++)
        #pragma unroll
        for (int j = 0; j < 4; j++) acc[i][j] = 0ULL;

    for (int k0 = 0; k0 < 256; k0 += 32) {
        #pragma unroll
        for (int i = 0; i < 8; i++) {
            int idx = tid + i*256;
            int kk = idx >> 6, r = idx & 63;
            Xs[kk][r] = hs[xbase[i] + k0*196];
        }
        #pragma unroll
        for (int i = 0; i < 16; i++) {
            int idx = tid + i*256;
            int kk = idx >> 7, oo = idx & 127;
            float w = g_wall[(k0+kk)*1536 + bo + oo];
            Ws2[kk][oo] = pack2(w, w);
        }
        __syncthreads();
        #pragma unroll
        for (int kk = 0; kk < 32; kk++) {
            ulonglong2 a01 = *reinterpret_cast<const ulonglong2*>(&Xs[kk][ty*8]);
            ulonglong2 a23 = *reinterpret_cast<const ulonglong2*>(&Xs[kk][ty*8+4]);
            ulonglong2 b01 = *reinterpret_cast<const ulonglong2*>(&Ws2[kk][tx*4]);
            ulonglong2 b23 = *reinterpret_cast<const ulonglong2*>(&Ws2[kk][tx*4+2]);
            acc[0][0] = ffma2(a01.x, b01.x, acc[0][0]);
            acc[0][1] = ffma2(a01.x, b01.y, acc[0][1]);
            acc[0][2] = ffma2(a01.x, b23.x, acc[0][2]);
            acc[0][3] = ffma2(a01.x, b23.y, acc[0][3]);
            acc[1][0] = ffma2(a01.y, b01.x, acc[1][0]);
            acc[1][1] = ffma2(a01.y, b01.y, acc[1][1]);
            acc[1][2] = ffma2(a01.y, b23.x, acc[1][2]);
            acc[1][3] = ffma2(a01.y, b23.y, acc[1][3]);
            acc[2][0] = ffma2(a23.x, b01.x, acc[2][0]);
            acc[2][1] = ffma2(a23.x, b01.y, acc[2][1]);
            acc[2][2] = ffma2(a23.x, b23.x, acc[2][2]);
            acc[2][3] = ffma2(a23.x, b23.y, acc[2][3]);
            acc[3][0] = ffma2(a23.y, b01.x, acc[3][0]);
            acc[3][1] = ffma2(a23.y, b01.y, acc[3][1]);
            acc[3][2] = ffma2(a23.y, b23.x, acc[3][2]);
            acc[3][3] = ffma2(a23.y, b23.y, acc[3][3]);
        }
        __syncthreads();
    }

    const int o4 = bo + tx*4;
    const float4 bia = *reinterpret_cast<const float4*>(&g_ball[o4]);
    #pragma unroll
    for (int ip = 0; ip < 4; ip++) {
        float2 f0 = unpack2(acc[ip][0]);
        float2 f1 = unpack2(acc[ip][1]);
        float2 f2 = unpack2(acc[ip][2]);
        float2 f3 = unpack2(acc[ip][3]);
        int r0 = rowBase + ty*8 + ip*2;     // always even
        float4 v0 = make_float4(f0.x+bia.x, f1.x+bia.y, f2.x+bia.z, f3.x+bia.w);
        float4 v1 = make_float4(f0.y+bia.x, f1.y+bia.y, f2.y+bia.z, f3.y+bia.w);
        if (bo < 256) {
            *reinterpret_cast<float4*>(&g_q[r0*256 + o4])     = v0;
            *reinterpret_cast<float4*>(&g_q[(r0+1)*256 + o4]) = v1;
        } else if (bo < 512) {
            // K paired layout: pair cp gets (c even, c odd) adjacent per m
            const int cp0 = (o4 - 256) >> 1;   // even
            #pragma unroll
            for (int lane = 0; lane < 2; lane++) {
                int row = r0 + lane;
                int b = row / 196, n = row - b*196;
                float2 p0 = (lane == 0) ? make_float2(v0.x, v0.y) : make_float2(v1.x, v1.y);
                float2 p1 = (lane == 0) ? make_float2(v0.z, v0.w) : make_float2(v1.z, v1.w);
                *reinterpret_cast<float2*>(&g_k[((b*128 + cp0)*196 + n)*2])     = p0;
                *reinterpret_cast<float2*>(&g_k[((b*128 + cp0 + 1)*196 + n)*2]) = p1;
            }
        } else {
            *reinterpret_cast<float4*>(&g_v[r0*1024 + o4-512])     = v0;
            *reinterpret_cast<float4*>(&g_v[(r0+1)*1024 + o4-512]) = v1;
            // interleaved copy for attn phase 4
            int b = r0 / 196, n = r0 - b*196, pm = n >> 1;
            float4 qA = make_float4(v0.x, v1.x, v0.y, v1.y);
            float4 qB = make_float4(v0.z, v1.z, v0.w, v1.w);
            float* vb2 = &g_v2[(((size_t)b*98 + pm)*1024 + (o4-512))*2];
            *reinterpret_cast<float4*>(vb2)     = qA;
            *reinterpret_cast<float4*>(vb2 + 4) = qB;
        }
    }
}

// ---------------- kernel 2: depthwise 3x3 conv, sliding window over x ------
__global__ __launch_bounds__(512) void dwconv_kernel(
    const float* __restrict__ wvl, const float* __restrict__ bvl,
    const float* __restrict__ svl, const float* __restrict__ tvl)
{
    const int b = blockIdx.y, y = blockIdx.x;
    const int c0 = threadIdx.x * 2;

    ull wt[9];
    #pragma unroll
    for (int k = 0; k < 9; k++) wt[k] = pack2(wvl[c0*9 + k], wvl[c0*9 + 9 + k]);
    float2 bv2 = make_float2(bvl[c0], bvl[c0+1]);
    float2 sv2 = make_float2(svl[c0], svl[c0+1]);
    float2 tv2 = make_float2(tvl[c0], tvl[c0+1]);

    const float* vbase = &g_v[(b*196)*1024 + c0];
    const bool rok0 = (y > 0), rok2 = (y < 13);
    const int r0off = (y-1)*14*1024, r1off = y*14*1024, r2off = (y+1)*14*1024;

    ull win[3][3];
    #pragma unroll
    for (int r = 0; r < 3; r++) win[r][0] = 0ULL;
    win[0][1] = rok0 ? *(const ull*)&vbase[r0off] : 0ULL;
    win[1][1] =        *(const ull*)&vbase[r1off];
    win[2][1] = rok2 ? *(const ull*)&vbase[r2off] : 0ULL;
    win[0][2] = rok0 ? *(const ull*)&vbase[r0off + 1024] : 0ULL;
    win[1][2] =        *(const ull*)&vbase[r1off + 1024];
    win[2][2] = rok2 ? *(const ull*)&vbase[r2off + 1024] : 0ULL;

    #pragma unroll
    for (int x = 0; x < 14; x++) {
        ull acc = 0ULL;
        #pragma unroll
        for (int r = 0; r < 3; r++)
            #pragma unroll
            for (int j = 0; j < 3; j++)
                acc = ffma2(win[r][j], wt[r*3 + j], acc);
        float2 f = unpack2(acc);
        float2 o;
        o.x = fmaf(f.x + bv2.x, sv2.x, tv2.x);
        o.y = fmaf(f.y + bv2.y, sv2.y, tv2.y);
        *reinterpret_cast<float2*>(&g_vl[(b*196 + y*14 + x)*1024 + c0]) = o;

        #pragma unroll
        for (int r = 0; r < 3; r++) { win[r][0] = win[r][1]; win[r][1] = win[r][2]; }
        if (x < 12) {
            int xo = (x+2)*1024;
            win[0][2] = rok0 ? *(const ull*)&vbase[r0off + xo] : 0ULL;
            win[1][2] =        *(const ull*)&vbase[r1off + xo];
            win[2][2] = rok2 ? *(const ull*)&vbase[r2off + xo] : 0ULL;
        } else {
            win[0][2] = 0ULL; win[1][2] = 0ULL; win[2][2] = 0ULL;
        }
    }
}

// ---------------- kernel 3: fused attention (512 thr, 7 q-rows, ping-pong) -
__global__ __launch_bounds__(512, 2) void attn_kernel(
    const float* __restrict__ th1, const float* __restrict__ bth1,
    const float* __restrict__ th2, const float* __restrict__ bth2,
    const int*   __restrict__ idxs)
{
    extern __shared__ __align__(16) float smem[];
    float* qs   = smem;             // 1792
    float* a3   = smem + 1792;      // 10976 raw logits / th2-mixed probs
    float* a2   = smem + 12768;     // 10976 th1-mixed logits / softmax probs
    float* abms = smem + 23744;     // 1568
    float* th1s = smem + 25312;     // 64 (pre-scaled)
    float* th2s = smem + 25376;     // 64
    float* bts  = smem + 25440;     // 16
    ull*   bt2u = reinterpret_cast<ull*>(smem + 25456);  // 8 ull

    const int tid = threadIdx.x;
    const int b  = blockIdx.y;
    const int n0 = blockIdx.x * 7;

    for (int idx = tid; idx < 1792; idx += 512)
        qs[idx] = g_q[(b*196 + n0 + (idx >> 8))*256 + (idx & 255)];
    for (int idx = tid; idx < 1568; idx += 512)
        abms[idx] = g_abm[idx];
    if (tid < 64) { th1s[tid] = th1[tid] * SCALE_; th2s[tid] = th2[tid]; }
    if (tid < 8)  { bts[tid] = bth1[tid]; bts[8 + tid] = bth2[tid];
                    bt2u[tid] = pack2(bth2[tid], bth2[tid]); }
    __syncthreads();

    // ---- phase 1: raw logits -> a3. item = (m, h), all 512 threads --------
    for (int it = tid; it < 1568; it += 512) {
        const int h = it / 196;
        const int m = it - h*196;
        // paired-K: base of pair cp = h*16, element (m, parity)
        const float* kb = &g_k[((b*128 + h*16)*196 + m)*2];
        ull s2[7];
        #pragma unroll
        for (int n = 0; n < 7; n++) s2[n] = 0ULL;
        #pragma unroll
        for (int c8 = 0; c8 < 8; c8++) {
            ull k01 = *reinterpret_cast<const ull*>(kb + c8*784);
            ull k23 = *reinterpret_cast<const ull*>(kb + c8*784 + 392);
            #pragma unroll
            for (int n = 0; n < 7; n++) {
                ulonglong2 q2 = *reinterpret_cast<const ulonglong2*>(&qs[n*256 + h*32 + c8*4]);
                s2[n] = ffma2(q2.x, k01, ffma2(q2.y, k23, s2[n]));
            }
        }
        #pragma unroll
        for (int n = 0; n < 7; n++) {
            float2 f = unpack2(s2[n]);
            a3[(n*8 + h)*196 + m] = f.x + f.y;
        }
    }
    __syncthreads();

    // ---- phase 1b: th1 mix + bias + ab : a3 -> a2 --------------------------
    {
        const int gp = tid >> 7;
        const int g0 = gp*2;
        ull wd0[8], wd1[8];
        #pragma unroll
        for (int h = 0; h < 8; h++) {
            float w0 = th1s[g0*8 + h], w1 = th1s[g0*8 + 8 + h];
            wd0[h] = pack2(w0, w0); wd1[h] = pack2(w1, w1);
        }
        const float bt0 = bts[g0], bt1 = bts[g0+1];
        const ull* a3u = reinterpret_cast<const ull*>(a3);
        ull* a2u = reinterpret_cast<ull*>(a2);
        for (int it = (tid & 127); it < 686; it += 128) {
            const int n = it / 98;
            const int pm = it - n*98;
            const int m0 = pm*2;
            int2 ixp = *reinterpret_cast<const int2*>(&idxs[(n0+n)*196 + m0]);
            ull t0 = pack2(bt0 + abms[g0*196 + ixp.x],     bt0 + abms[g0*196 + ixp.y]);
            ull t1 = pack2(bt1 + abms[(g0+1)*196 + ixp.x], bt1 + abms[(g0+1)*196 + ixp.y]);
            const ull* pb = a3u + n*784 + pm;
            #pragma unroll
            for (int h = 0; h < 8; h++) {
                ull p2 = pb[h*98];
                t0 = ffma2(p2, wd0[h], t0);
                t1 = ffma2(p2, wd1[h], t1);
            }
            a2u[(n*8 + g0)*98 + pm]     = t0;
            a2u[(n*8 + g0 + 1)*98 + pm] = t1;
        }
    }
    __syncthreads();

    // ---- phase 2: softmax on a2 (paired) -----------------------------------
    {
        const int w = tid >> 5, lane = tid & 31;
        for (int r = w; r < 56; r += 16) {
            ull* rowu = reinterpret_cast<ull*>(a2 + r*196);
            float mx = -1e30f;
            for (int i = lane; i < 98; i += 32) {
                float2 f = unpack2(rowu[i]);
                mx = fmaxf(mx, fmaxf(f.x, f.y));
            }
            #pragma unroll
            for (int off = 16; off > 0; off >>= 1)
                mx = fmaxf(mx, __shfl_xor_sync(0xffffffffu, mx, off));
            ull sm2 = 0ULL;
            for (int i = lane; i < 98; i += 32) {
                float2 f = unpack2(rowu[i]);
                f.x = __expf(f.x - mx); f.y = __expf(f.y - mx);
                ull e = pack2(f.x, f.y);
                rowu[i] = e;
                sm2 = fadd2(sm2, e);
            }
            float2 fs = unpack2(sm2);
            float sm = fs.x + fs.y;
            #pragma unroll
            for (int off = 16; off > 0; off >>= 1)
                sm += __shfl_xor_sync(0xffffffffu, sm, off);
            float inv = 1.f / sm;
            ull inv2 = pack2(inv, inv);
            for (int i = lane; i < 98; i += 32) rowu[i] = fmul2(rowu[i], inv2);
        }
    }
    __syncthreads();

    // ---- phase 3: th2 mix + bias : a2 -> a3 --------------------------------
    {
        const int gp = tid >> 7;
        const int g0 = gp*2;
        ull wd0[8], wd1[8];
        #pragma unroll
        for (int h = 0; h < 8; h++) {
            float w0 = th2s[g0*8 + h], w1 = th2s[g0*8 + 8 + h];
            wd0[h] = pack2(w0, w0); wd1[h] = pack2(w1, w1);
        }
        const ull bt0 = bt2u[g0], bt1 = bt2u[g0+1];
        const ull* a2u = reinterpret_cast<const ull*>(a2);
        ull* a3u = reinterpret_cast<ull*>(a3);
        for (int it = (tid & 127); it < 686; it += 128) {
            const int n = it / 98;
            const int pm = it - n*98;
            ull t0 = bt0, t1 = bt1;
            const ull* pb = a2u + n*784 + pm;
            #pragma unroll
            for (int h = 0; h < 8; h++) {
                ull p2 = pb[h*98];
                t0 = ffma2(p2, wd0[h], t0);
                t1 = ffma2(p2, wd1[h], t1);
            }
            a3u[(n*8 + g0)*98 + pm]     = t0;
            a3u[(n*8 + g0 + 1)*98 + pm] = t1;
        }
    }
    __syncthreads();

    // ---- phase 4: attn @ V + vl add + exact gelu ---------------------------
    {
        const int head = tid >> 6;
        const int c0 = head*128 + (tid & 63)*2;
        ull accA[7], accB[7];
        #pragma unroll
        for (int n = 0; n < 7; n++) { accA[n] = 0ULL; accB[n] = 0ULL; }

        const ull* pbase = reinterpret_cast<const ull*>(a3) + head*98;
        const float* vb2 = &g_v2[((size_t)(b*98)*1024 + c0)*2];
        #pragma unroll 7
        for (int pm = 0; pm < 98; pm++) {
            ulonglong2 vv = *reinterpret_cast<const ulonglong2*>(vb2 + (size_t)pm*2048);
            #pragma unroll
            for (int n = 0; n < 7; n++) {
                ull p = pbase[n*784 + pm];
                accA[n] = ffma2(p, vv.x, accA[n]);
                accB[n] = ffma2(p, vv.y, accB[n]);
            }
        }
        #pragma unroll
        for (int n = 0; n < 7; n++) {
            int off = (b*196 + n0 + n)*1024 + c0;
            float2 vl2 = *reinterpret_cast<const float2*>(&g_vl[off]);
            float2 fA = unpack2(accA[n]);
            float2 fB = unpack2(accB[n]);
            float a0 = fA.x + fA.y + vl2.x;
            float a1 = fB.x + fB.y + vl2.y;
            float2 o2;
            o2.x = 0.5f * a0 * (1.f + erff(a0 * 0.7071067811865476f));
            o2.y = 0.5f * a1 * (1.f + erff(a1 * 0.7071067811865476f));
            *reinterpret_cast<float2*>(&g_ao[off]) = o2;
        }
    }
}

// ---------------- kernel 4: output projection GEMM -------------------------
// Activation operand pre-duplicated in smem -> zero pack MOVs in loop.
__global__ __launch_bounds__(256, 2) void outproj_kernel(float* __restrict__ out)
{
    __shared__ __align__(16) float As[32][64];
    __shared__ __align__(16) ull   Bs2[32][132];
    const int tid = threadIdx.x;
    const int tx = tid & 31, ty = tid >> 5;
    const int row0 = blockIdx.x * 128;
    const int o0 = blockIdx.y * 64;

    ull acc[4][4];
    #pragma unroll
    for (int i = 0; i < 4; i++)
        #pragma unroll
        for (int j = 0; j < 4; j++) acc[i][j] = 0ULL;

    for (int k0 = 0; k0 < 1024; k0 += 32) {
        #pragma unroll
        for (int i = 0; i < 8; i++) {
            int idx = tid + i*256;
            int kk = idx >> 6, o = idx & 63;
            As[kk][o] = g_wp[(k0+kk)*256 + o0 + o];
        }
        {
            int kk4 = (tid & 7) * 4;
            int rb = tid >> 3;
            #pragma unroll
            for (int i = 0; i < 4; i++) {
                int r = rb + i*32;
                float4 x4 = *reinterpret_cast<const float4*>(&g_ao[(row0+r)*1024 + k0 + kk4]);
                Bs2[kk4+0][r] = pack2(x4.x, x4.x);
                Bs2[kk4+1][r] = pack2(x4.y, x4.y);
                Bs2[kk4+2][r] = pack2(x4.z, x4.z);
                Bs2[kk4+3][r] = pack2(x4.w, x4.w);
            }
        }
        __syncthreads();
        #pragma unroll
        for (int kk = 0; kk < 32; kk++) {
            ulonglong2 a01 = *reinterpret_cast<const ulonglong2*>(&As[kk][ty*8]);
            ulonglong2 a23 = *reinterpret_cast<const ulonglong2*>(&As[kk][ty*8+4]);
            ulonglong2 b01 = *reinterpret_cast<const ulonglong2*>(&Bs2[kk][tx*4]);
            ulonglong2 b23 = *reinterpret_cast<const ulonglong2*>(&Bs2[kk][tx*4+2]);
            acc[0][0] = ffma2(a01.x, b01.x, acc[0][0]);
            acc[0][1] = ffma2(a01.x, b01.y, acc[0][1]);
            acc[0][2] = ffma2(a01.x, b23.x, acc[0][2]);
            acc[0][3] = ffma2(a01.x, b23.y, acc[0][3]);
            acc[1][0] = ffma2(a01.y, b01.x, acc[1][0]);
            acc[1][1] = ffma2(a01.y, b01.y, acc[1][1]);
            acc[1][2] = ffma2(a01.y, b23.x, acc[1][2]);
            acc[1][3] = ffma2(a01.y, b23.y, acc[1][3]);
            acc[2][0] = ffma2(a23.x, b01.x, acc[2][0]);
            acc[2][1] = ffma2(a23.x, b01.y, acc[2][1]);
            acc[2][2] = ffma2(a23.x, b23.x, acc[2][2]);
            acc[2][3] = ffma2(a23.x, b23.y, acc[2][3]);
            acc[3][0] = ffma2(a23.y, b01.x, acc[3][0]);
            acc[3][1] = ffma2(a23.y, b01.y, acc[3][1]);
            acc[3][2] = ffma2(a23.y, b23.x, acc[3][2]);
            acc[3][3] = ffma2(a23.y, b23.y, acc[3][3]);
        }
        __syncthreads();
    }

    const int row = row0 + tx*4;
    const int b = row / 196, n = row - b*196;
    #pragma unroll
    for (int ip = 0; ip < 4; ip++) {
        float2 f0 = unpack2(acc[ip][0]);
        float2 f1 = unpack2(acc[ip][1]);
        float2 f2 = unpack2(acc[ip][2]);
        float2 f3 = unpack2(acc[ip][3]);
        int oA = o0 + ty*8 + ip*2;
        float biasA = g_bp[oA], biasB = g_bp[oA+1];
        float4 vA = make_float4(f0.x+biasA, f1.x+biasA, f2.x+biasA, f3.x+biasA);
        float4 vB = make_float4(f0.y+biasB, f1.y+biasB, f2.y+biasB, f3.y+biasB);
        *reinterpret_cast<float4*>(&out[b*50176 + oA*196 + n])     = vA;
        *reinterpret_cast<float4*>(&out[b*50176 + (oA+1)*196 + n]) = vB;
    }
}

// ---------------- launch ----------------------------------------------------
extern "C" void kernel_launch(void* const* d_in, const int* in_sizes, int n_in,
                              void* d_out, int out_size)
{
    const float* hs   = (const float*)d_in[0];
    const float* wq   = (const float*)d_in[1];
    const float* bq   = (const float*)d_in[2];
    const float* sq   = (const float*)d_in[3];
    const float* tq   = (const float*)d_in[4];
    const float* wk   = (const float*)d_in[5];
    const float* bk   = (const float*)d_in[6];
    const float* sk   = (const float*)d_in[7];
    const float* tk   = (const float*)d_in[8];
    const float* wv   = (const float*)d_in[9];
    const float* bv   = (const float*)d_in[10];
    const float* sv   = (const float*)d_in[11];
    const float* tv   = (const float*)d_in[12];
    const float* wvl  = (const float*)d_in[13];
    const float* bvl  = (const float*)d_in[14];
    const float* svl  = (const float*)d_in[15];
    const float* tvl  = (const float*)d_in[16];
    const float* th1  = (const float*)d_in[17];
    const float* bth1 = (const float*)d_in[18];
    const float* th2  = (const float*)d_in[19];
    const float* bth2 = (const float*)d_in[20];
    const float* wp   = (const float*)d_in[21];
    const float* bp   = (const float*)d_in[22];
    const float* sp   = (const float*)d_in[23];
    const float* tp   = (const float*)d_in[24];
    const float* ab   = (const float*)d_in[25];
    const int*   bidx = (const int*)d_in[26];

    cudaFuncSetAttribute(attn_kernel, cudaFuncAttributeMaxDynamicSharedMemorySize, 101888);

    const int pre_total = DIM_*QKV_ + DH_*DIM_ + QKV_ + 256 + H_*NOFF_;
    precompute_kernel<<<(pre_total + 255)/256, 256>>>(
        wq,bq,sq,tq, wk,bk,sk,tk, wv,bv,sv,tv, wp,bp,sp,tp, th1, ab);

    proj_kernel<<<dim3(392, 12), 256>>>(hs);
    dwconv_kernel<<<dim3(14, 128), 512>>>(wvl, bvl, svl, tvl);
    attn_kernel<<<dim3(28, 128), 512, 101888>>>(th1, bth1, th2, bth2, bidx);
    outproj_kernel<<<dim3(196, 4), 256>>>((float*)d_out);
}

// round 12
// speedup vs baseline: 1.5039x; 1.5039x over previous
#include <cuda_runtime.h>
#include <math.h>

// Problem constants
#define RES_ 14
#define N_ 196
#define B_ 128
#define DIM_ 256
#define H_ 8
#define KD_ 32
#define DV_ 128
#define DH_ 1024
#define NOFF_ 196
#define QKV_ 1536
#define SCALE_ 0.17677669529663687f

typedef unsigned long long ull;

// ---- packed fp32x2 helpers -------------------------------------------------
__device__ __forceinline__ ull ffma2(ull a, ull b, ull c) {
    ull d; asm("fma.rn.f32x2 %0, %1, %2, %3;" : "=l"(d) : "l"(a), "l"(b), "l"(c)); return d;
}
__device__ __forceinline__ ull fadd2(ull a, ull b) {
    ull d; asm("add.rn.f32x2 %0, %1, %2;" : "=l"(d) : "l"(a), "l"(b)); return d;
}
__device__ __forceinline__ ull fmul2(ull a, ull b) {
    ull d; asm("mul.rn.f32x2 %0, %1, %2;" : "=l"(d) : "l"(a), "l"(b)); return d;
}
__device__ __forceinline__ ull pack2(float lo, float hi) {
    ull d; asm("mov.b64 %0, {%1, %2};" : "=l"(d) : "f"(lo), "f"(hi)); return d;
}
__device__ __forceinline__ float2 unpack2(ull d) {
    float2 r; asm("mov.b64 {%0, %1}, %2;" : "=f"(r.x), "=f"(r.y) : "l"(d)); return r;
}

// ---------------- scratch (static device globals) --------------------------
__device__ __align__(16) float g_wall[DIM_*QKV_];
__device__ __align__(16) float g_ball[QKV_];
__device__ __align__(16) float g_wp[DH_*DIM_];
__device__ __align__(16) float g_bp[DIM_];
__device__ __align__(16) float g_abm[H_*NOFF_];
__device__ __align__(16) float g_q [B_*N_*256];     // (b,n,c)
// K paired layout: g_k[((b*128 + cp)*196 + m)*2 + par], cp=c/2, par=c&1
__device__ __align__(16) float g_k [B_*256*N_];
__device__ __align__(16) float g_v [B_*N_*DH_];     // (b,n,c) — for dwconv
// V interleaved: g_v2[((b*98+pm)*1024 + c0)*2 + {0..3}] = (c0_e, c0_o, c1_e, c1_o)
__device__ __align__(16) float g_v2[B_*N_*DH_];
__device__ __align__(16) float g_vl[B_*N_*DH_];
__device__ __align__(16) float g_ao[B_*N_*DH_];     // gelu(attn_out + vl)

// ---------------- kernel 0: fold scales / mix biases ------------------------
__global__ void precompute_kernel(
    const float* __restrict__ wq, const float* __restrict__ bq,
    const float* __restrict__ sq, const float* __restrict__ tq,
    const float* __restrict__ wk, const float* __restrict__ bk,
    const float* __restrict__ sk, const float* __restrict__ tk,
    const float* __restrict__ wv, const float* __restrict__ bv,
    const float* __restrict__ sv, const float* __restrict__ tv,
    const float* __restrict__ wp, const float* __restrict__ bp,
    const float* __restrict__ sp, const float* __restrict__ tp,
    const float* __restrict__ th1, const float* __restrict__ ab)
{
    int i = blockIdx.x * blockDim.x + threadIdx.x;
    if (i < DIM_*QKV_) {
        int c = i / QKV_, o = i % QKV_;
        float w;
        if (o < 256)       w = wq[c*256 + o]        * sq[o];
        else if (o < 512)  w = wk[c*256 + (o-256)]  * sk[o-256];
        else               w = wv[c*1024 + (o-512)] * sv[o-512];
        g_wall[i] = w;
        return;
    }
    int j = i - DIM_*QKV_;
    if (j < DH_*DIM_) {
        int c = j / 256, o = j % 256;
        g_wp[j] = wp[c*256 + o] * sp[o];
        return;
    }
    int l = j - DH_*DIM_;
    if (l < QKV_) {
        float v;
        if (l < 256)       v = bq[l]*sq[l] + tq[l];
        else if (l < 512)  v = bk[l-256]*sk[l-256] + tk[l-256];
        else               v = bv[l-512]*sv[l-512] + tv[l-512];
        g_ball[l] = v;
        return;
    }
    int m2 = l - QKV_;
    if (m2 < 256) { g_bp[m2] = bp[m2]*sp[m2] + tp[m2]; return; }
    int a = m2 - 256;
    if (a < H_*NOFF_) {
        int g = a / NOFF_, f = a % NOFF_;
        float s = 0.f;
        #pragma unroll
        for (int h = 0; h < 8; h++) s = fmaf(th1[g*8+h], ab[h*NOFF_ + f], s);
        g_abm[a] = s;
    }
}

// ---------------- kernel 1: fused QKV projection GEMM (64x128 tile) --------
__global__ __launch_bounds__(256, 2) void proj_kernel(const float* __restrict__ hs)
{
    __shared__ __align__(16) float Xs[32][64];
    __shared__ __align__(16) float Ws[32][128];
    const int tid = threadIdx.x;
    const int tx = tid & 31, ty = tid >> 5;
    const int rowBase = blockIdx.x * 64;
    const int bo = blockIdx.y * 128;

    int xbase[8];
    #pragma unroll
    for (int i = 0; i < 8; i++) {
        int idx = tid + i*256;
        int kk = idx >> 6, r = idx & 63;
        int row = rowBase + r;
        int b = row / 196, n = row - b*196;
        xbase[i] = b*50176 + kk*196 + n;
    }

    ull acc[4][4];
    #pragma unroll
    for (int i = 0; i < 4; i++)
        #pragma unroll
        for (int j = 0; j < 4; j++) acc[i][j] = 0ULL;

    for (int k0 = 0; k0 < 256; k0 += 32) {
        #pragma unroll
        for (int i = 0; i < 8; i++) {
            int idx = tid + i*256;
            int kk = idx >> 6, r = idx & 63;
            Xs[kk][r] = hs[xbase[i] + k0*196];
        }
        #pragma unroll
        for (int i = 0; i < 16; i++) {
            int idx = tid + i*256;
            int kk = idx >> 7, oo = idx & 127;
            Ws[kk][oo] = g_wall[(k0+kk)*1536 + bo + oo];
        }
        __syncthreads();
        #pragma unroll
        for (int kk = 0; kk < 32; kk++) {
            ulonglong2 a01 = *reinterpret_cast<const ulonglong2*>(&Xs[kk][ty*8]);
            ulonglong2 a23 = *reinterpret_cast<const ulonglong2*>(&Xs[kk][ty*8+4]);
            float4 b4 = *reinterpret_cast<const float4*>(&Ws[kk][tx*4]);
            ull bb0 = pack2(b4.x, b4.x), bb1 = pack2(b4.y, b4.y);
            ull bb2 = pack2(b4.z, b4.z), bb3 = pack2(b4.w, b4.w);
            acc[0][0] = ffma2(a01.x, bb0, acc[0][0]);
            acc[0][1] = ffma2(a01.x, bb1, acc[0][1]);
            acc[0][2] = ffma2(a01.x, bb2, acc[0][2]);
            acc[0][3] = ffma2(a01.x, bb3, acc[0][3]);
            acc[1][0] = ffma2(a01.y, bb0, acc[1][0]);
            acc[1][1] = ffma2(a01.y, bb1, acc[1][1]);
            acc[1][2] = ffma2(a01.y, bb2, acc[1][2]);
            acc[1][3] = ffma2(a01.y, bb3, acc[1][3]);
            acc[2][0] = ffma2(a23.x, bb0, acc[2][0]);
            acc[2][1] = ffma2(a23.x, bb1, acc[2][1]);
            acc[2][2] = ffma2(a23.x, bb2, acc[2][2]);
            acc[2][3] = ffma2(a23.x, bb3, acc[2][3]);
            acc[3][0] = ffma2(a23.y, bb0, acc[3][0]);
            acc[3][1] = ffma2(a23.y, bb1, acc[3][1]);
            acc[3][2] = ffma2(a23.y, bb2, acc[3][2]);
            acc[3][3] = ffma2(a23.y, bb3, acc[3][3]);
        }
        __syncthreads();
    }

    const int o4 = bo + tx*4;
    const float4 bia = *reinterpret_cast<const float4*>(&g_ball[o4]);
    #pragma unroll
    for (int ip = 0; ip < 4; ip++) {
        float2 f0 = unpack2(acc[ip][0]);
        float2 f1 = unpack2(acc[ip][1]);
        float2 f2 = unpack2(acc[ip][2]);
        float2 f3 = unpack2(acc[ip][3]);
        int r0 = rowBase + ty*8 + ip*2;     // always even
        float4 v0 = make_float4(f0.x+bia.x, f1.x+bia.y, f2.x+bia.z, f3.x+bia.w);
        float4 v1 = make_float4(f0.y+bia.x, f1.y+bia.y, f2.y+bia.z, f3.y+bia.w);
        if (bo < 256) {
            *reinterpret_cast<float4*>(&g_q[r0*256 + o4])     = v0;
            *reinterpret_cast<float4*>(&g_q[(r0+1)*256 + o4]) = v1;
        } else if (bo < 512) {
            // K paired layout: pair cp gets (c even, c odd) adjacent per m
            const int cp0 = (o4 - 256) >> 1;   // even
            #pragma unroll
            for (int lane = 0; lane < 2; lane++) {
                int row = r0 + lane;
                int b = row / 196, n = row - b*196;
                float2 p0 = (lane == 0) ? make_float2(v0.x, v0.y) : make_float2(v1.x, v1.y);
                float2 p1 = (lane == 0) ? make_float2(v0.z, v0.w) : make_float2(v1.z, v1.w);
                *reinterpret_cast<float2*>(&g_k[((b*128 + cp0)*196 + n)*2])     = p0;
                *reinterpret_cast<float2*>(&g_k[((b*128 + cp0 + 1)*196 + n)*2]) = p1;
            }
        } else {
            *reinterpret_cast<float4*>(&g_v[r0*1024 + o4-512])     = v0;
            *reinterpret_cast<float4*>(&g_v[(r0+1)*1024 + o4-512]) = v1;
            // interleaved copy for attn phase 4
            int b = r0 / 196, n = r0 - b*196, pm = n >> 1;
            float4 qA = make_float4(v0.x, v1.x, v0.y, v1.y);
            float4 qB = make_float4(v0.z, v1.z, v0.w, v1.w);
            float* vb2 = &g_v2[(((size_t)b*98 + pm)*1024 + (o4-512))*2];
            *reinterpret_cast<float4*>(vb2)     = qA;
            *reinterpret_cast<float4*>(vb2 + 4) = qB;
        }
    }
}

// ---------------- kernel 2: depthwise 3x3 conv, sliding window over x ------
__global__ __launch_bounds__(512) void dwconv_kernel(
    const float* __restrict__ wvl, const float* __restrict__ bvl,
    const float* __restrict__ svl, const float* __restrict__ tvl)
{
    const int b = blockIdx.y, y = blockIdx.x;
    const int c0 = threadIdx.x * 2;

    ull wt[9];
    #pragma unroll
    for (int k = 0; k < 9; k++) wt[k] = pack2(wvl[c0*9 + k], wvl[c0*9 + 9 + k]);
    float2 bv2 = make_float2(bvl[c0], bvl[c0+1]);
    float2 sv2 = make_float2(svl[c0], svl[c0+1]);
    float2 tv2 = make_float2(tvl[c0], tvl[c0+1]);

    const float* vbase = &g_v[(b*196)*1024 + c0];
    const bool rok0 = (y > 0), rok2 = (y < 13);
    const int r0off = (y-1)*14*1024, r1off = y*14*1024, r2off = (y+1)*14*1024;

    ull win[3][3];
    #pragma unroll
    for (int r = 0; r < 3; r++) win[r][0] = 0ULL;
    win[0][1] = rok0 ? *(const ull*)&vbase[r0off] : 0ULL;
    win[1][1] =        *(const ull*)&vbase[r1off];
    win[2][1] = rok2 ? *(const ull*)&vbase[r2off] : 0ULL;
    win[0][2] = rok0 ? *(const ull*)&vbase[r0off + 1024] : 0ULL;
    win[1][2] =        *(const ull*)&vbase[r1off + 1024];
    win[2][2] = rok2 ? *(const ull*)&vbase[r2off + 1024] : 0ULL;

    #pragma unroll
    for (int x = 0; x < 14; x++) {
        ull acc = 0ULL;
        #pragma unroll
        for (int r = 0; r < 3; r++)
            #pragma unroll
            for (int j = 0; j < 3; j++)
                acc = ffma2(win[r][j], wt[r*3 + j], acc);
        float2 f = unpack2(acc);
        float2 o;
        o.x = fmaf(f.x + bv2.x, sv2.x, tv2.x);
        o.y = fmaf(f.y + bv2.y, sv2.y, tv2.y);
        *reinterpret_cast<float2*>(&g_vl[(b*196 + y*14 + x)*1024 + c0]) = o;

        #pragma unroll
        for (int r = 0; r < 3; r++) { win[r][0] = win[r][1]; win[r][1] = win[r][2]; }
        if (x < 12) {
            int xo = (x+2)*1024;
            win[0][2] = rok0 ? *(const ull*)&vbase[r0off + xo] : 0ULL;
            win[1][2] =        *(const ull*)&vbase[r1off + xo];
            win[2][2] = rok2 ? *(const ull*)&vbase[r2off + xo] : 0ULL;
        } else {
            win[0][2] = 0ULL; win[1][2] = 0ULL; win[2][2] = 0ULL;
        }
    }
}

// ---------------- kernel 3: fused attention (512 thr, 7 q-rows, ping-pong) -
__global__ __launch_bounds__(512, 2) void attn_kernel(
    const float* __restrict__ th1, const float* __restrict__ bth1,
    const float* __restrict__ th2, const float* __restrict__ bth2,
    const int*   __restrict__ idxs)
{
    extern __shared__ __align__(16) float smem[];
    float* qs   = smem;             // 1792
    float* a3   = smem + 1792;      // 10976 raw logits / th2-mixed probs
    float* a2   = smem + 12768;     // 10976 th1-mixed logits / softmax probs
    float* abms = smem + 23744;     // 1568
    float* th1s = smem + 25312;     // 64 (pre-scaled)
    float* th2s = smem + 25376;     // 64
    float* bts  = smem + 25440;     // 16
    ull*   bt2u = reinterpret_cast<ull*>(smem + 25456);  // 8 ull

    const int tid = threadIdx.x;
    const int b  = blockIdx.y;
    const int n0 = blockIdx.x * 7;

    for (int idx = tid; idx < 1792; idx += 512)
        qs[idx] = g_q[(b*196 + n0 + (idx >> 8))*256 + (idx & 255)];
    for (int idx = tid; idx < 1568; idx += 512)
        abms[idx] = g_abm[idx];
    if (tid < 64) { th1s[tid] = th1[tid] * SCALE_; th2s[tid] = th2[tid]; }
    if (tid < 8)  { bts[tid] = bth1[tid]; bts[8 + tid] = bth2[tid];
                    bt2u[tid] = pack2(bth2[tid], bth2[tid]); }
    __syncthreads();

    // ---- phase 1: raw logits -> a3. item = (m, h), all 512 threads --------
    for (int it = tid; it < 1568; it += 512) {
        const int h = it / 196;
        const int m = it - h*196;
        // paired-K: base of pair cp = h*16, element (m, parity)
        const float* kb = &g_k[((b*128 + h*16)*196 + m)*2];
        ull s2[7];
        #pragma unroll
        for (int n = 0; n < 7; n++) s2[n] = 0ULL;
        #pragma unroll
        for (int c8 = 0; c8 < 8; c8++) {
            ull k01 = *reinterpret_cast<const ull*>(kb + c8*784);
            ull k23 = *reinterpret_cast<const ull*>(kb + c8*784 + 392);
            #pragma unroll
            for (int n = 0; n < 7; n++) {
                ulonglong2 q2 = *reinterpret_cast<const ulonglong2*>(&qs[n*256 + h*32 + c8*4]);
                s2[n] = ffma2(q2.x, k01, ffma2(q2.y, k23, s2[n]));
            }
        }
        #pragma unroll
        for (int n = 0; n < 7; n++) {
            float2 f = unpack2(s2[n]);
            a3[(n*8 + h)*196 + m] = f.x + f.y;
        }
    }
    __syncthreads();

    // ---- phase 1b: th1 mix + bias + ab : a3 -> a2 --------------------------
    {
        const int gp = tid >> 7;
        const int g0 = gp*2;
        ull wd0[8], wd1[8];
        #pragma unroll
        for (int h = 0; h < 8; h++) {
            float w0 = th1s[g0*8 + h], w1 = th1s[g0*8 + 8 + h];
            wd0[h] = pack2(w0, w0); wd1[h] = pack2(w1, w1);
        }
        const float bt0 = bts[g0], bt1 = bts[g0+1];
        const ull* a3u = reinterpret_cast<const ull*>(a3);
        ull* a2u = reinterpret_cast<ull*>(a2);
        for (int it = (tid & 127); it < 686; it += 128) {
            const int n = it / 98;
            const int pm = it - n*98;
            const int m0 = pm*2;
            int2 ixp = *reinterpret_cast<const int2*>(&idxs[(n0+n)*196 + m0]);
            ull t0 = pack2(bt0 + abms[g0*196 + ixp.x],     bt0 + abms[g0*196 + ixp.y]);
            ull t1 = pack2(bt1 + abms[(g0+1)*196 + ixp.x], bt1 + abms[(g0+1)*196 + ixp.y]);
            const ull* pb = a3u + n*784 + pm;
            #pragma unroll
            for (int h = 0; h < 8; h++) {
                ull p2 = pb[h*98];
                t0 = ffma2(p2, wd0[h], t0);
                t1 = ffma2(p2, wd1[h], t1);
            }
            a2u[(n*8 + g0)*98 + pm]     = t0;
            a2u[(n*8 + g0 + 1)*98 + pm] = t1;
        }
    }
    __syncthreads();

    // ---- phase 2: softmax on a2 (paired) -----------------------------------
    {
        const int w = tid >> 5, lane = tid & 31;
        for (int r = w; r < 56; r += 16) {
            ull* rowu = reinterpret_cast<ull*>(a2 + r*196);
            float mx = -1e30f;
            for (int i = lane; i < 98; i += 32) {
                float2 f = unpack2(rowu[i]);
                mx = fmaxf(mx, fmaxf(f.x, f.y));
            }
            #pragma unroll
            for (int off = 16; off > 0; off >>= 1)
                mx = fmaxf(mx, __shfl_xor_sync(0xffffffffu, mx, off));
            ull sm2 = 0ULL;
            for (int i = lane; i < 98; i += 32) {
                float2 f = unpack2(rowu[i]);
                f.x = __expf(f.x - mx); f.y = __expf(f.y - mx);
                ull e = pack2(f.x, f.y);
                rowu[i] = e;
                sm2 = fadd2(sm2, e);
            }
            float2 fs = unpack2(sm2);
            float sm = fs.x + fs.y;
            #pragma unroll
            for (int off = 16; off > 0; off >>= 1)
                sm += __shfl_xor_sync(0xffffffffu, sm, off);
            float inv = 1.f / sm;
            ull inv2 = pack2(inv, inv);
            for (int i = lane; i < 98; i += 32) rowu[i] = fmul2(rowu[i], inv2);
        }
    }
    __syncthreads();

    // ---- phase 3: th2 mix + bias : a2 -> a3 --------------------------------
    {
        const int gp = tid >> 7;
        const int g0 = gp*2;
        ull wd0[8], wd1[8];
        #pragma unroll
        for (int h = 0; h < 8; h++) {
            float w0 = th2s[g0*8 + h], w1 = th2s[g0*8 + 8 + h];
            wd0[h] = pack2(w0, w0); wd1[h] = pack2(w1, w1);
        }
        const ull bt0 = bt2u[g0], bt1 = bt2u[g0+1];
        const ull* a2u = reinterpret_cast<const ull*>(a2);
        ull* a3u = reinterpret_cast<ull*>(a3);
        for (int it = (tid & 127); it < 686; it += 128) {
            const int n = it / 98;
            const int pm = it - n*98;
            ull t0 = bt0, t1 = bt1;
            const ull* pb = a2u + n*784 + pm;
            #pragma unroll
            for (int h = 0; h < 8; h++) {
                ull p2 = pb[h*98];
                t0 = ffma2(p2, wd0[h], t0);
                t1 = ffma2(p2, wd1[h], t1);
            }
            a3u[(n*8 + g0)*98 + pm]     = t0;
            a3u[(n*8 + g0 + 1)*98 + pm] = t1;
        }
    }
    __syncthreads();

    // ---- phase 4: attn @ V + vl add + exact gelu ---------------------------
    // 2 pm per step: prob pair via ONE broadcast LDS.128 (1 wavefront vs 2).
    {
        const int head = tid >> 6;
        const int c0 = head*128 + (tid & 63)*2;
        ull accA[7], accB[7];
        #pragma unroll
        for (int n = 0; n < 7; n++) { accA[n] = 0ULL; accB[n] = 0ULL; }

        const ull* pbase = reinterpret_cast<const ull*>(a3) + head*98;
        const float* vb2 = &g_v2[((size_t)(b*98)*1024 + c0)*2];
        for (int pm = 0; pm < 98; pm += 2) {
            ulonglong2 vv0 = *reinterpret_cast<const ulonglong2*>(vb2 + (size_t)pm*2048);
            ulonglong2 vv1 = *reinterpret_cast<const ulonglong2*>(vb2 + (size_t)(pm+1)*2048);
            #pragma unroll
            for (int n = 0; n < 7; n++) {
                ulonglong2 pp = *reinterpret_cast<const ulonglong2*>(&pbase[n*784 + pm]);
                accA[n] = ffma2(pp.x, vv0.x, accA[n]);
                accB[n] = ffma2(pp.x, vv0.y, accB[n]);
                accA[n] = ffma2(pp.y, vv1.x, accA[n]);
                accB[n] = ffma2(pp.y, vv1.y, accB[n]);
            }
        }
        #pragma unroll
        for (int n = 0; n < 7; n++) {
            int off = (b*196 + n0 + n)*1024 + c0;
            float2 vl2 = *reinterpret_cast<const float2*>(&g_vl[off]);
            float2 fA = unpack2(accA[n]);
            float2 fB = unpack2(accB[n]);
            float a0 = fA.x + fA.y + vl2.x;
            float a1 = fB.x + fB.y + vl2.y;
            float2 o2;
            o2.x = 0.5f * a0 * (1.f + erff(a0 * 0.7071067811865476f));
            o2.y = 0.5f * a1 * (1.f + erff(a1 * 0.7071067811865476f));
            *reinterpret_cast<float2*>(&g_ao[off]) = o2;
        }
    }
}

// ---------------- kernel 4: output projection GEMM -------------------------
__global__ __launch_bounds__(256, 2) void outproj_kernel(float* __restrict__ out)
{
    __shared__ __align__(16) float As[32][64];
    __shared__ __align__(16) float Bs[32][132];
    const int tid = threadIdx.x;
    const int tx = tid & 31, ty = tid >> 5;
    const int row0 = blockIdx.x * 128;
    const int o0 = blockIdx.y * 64;

    ull acc[4][4];
    #pragma unroll
    for (int i = 0; i < 4; i++)
        #pragma unroll
        for (int j = 0; j < 4; j++) acc[i][j] = 0ULL;

    for (int k0 = 0; k0 < 1024; k0 += 32) {
        #pragma unroll
        for (int i = 0; i < 8; i++) {
            int idx = tid + i*256;
            int kk = idx >> 6, o = idx & 63;
            As[kk][o] = g_wp[(k0+kk)*256 + o0 + o];
        }
        {
            int kk4 = (tid & 7) * 4;
            int rb = tid >> 3;
            #pragma unroll
            for (int i = 0; i < 4; i++) {
                int r = rb + i*32;
                float4 x4 = *reinterpret_cast<const float4*>(&g_ao[(row0+r)*1024 + k0 + kk4]);
                Bs[kk4+0][r] = x4.x; Bs[kk4+1][r] = x4.y;
                Bs[kk4+2][r] = x4.z; Bs[kk4+3][r] = x4.w;
            }
        }
        __syncthreads();
        #pragma unroll
        for (int kk = 0; kk < 32; kk++) {
            ulonglong2 a01 = *reinterpret_cast<const ulonglong2*>(&As[kk][ty*8]);
            ulonglong2 a23 = *reinterpret_cast<const ulonglong2*>(&As[kk][ty*8+4]);
            float4 b4 = *reinterpret_cast<const float4*>(&Bs[kk][tx*4]);
            ull bb0 = pack2(b4.x, b4.x), bb1 = pack2(b4.y, b4.y);
            ull bb2 = pack2(b4.z, b4.z), bb3 = pack2(b4.w, b4.w);
            acc[0][0] = ffma2(a01.x, bb0, acc[0][0]);
            acc[0][1] = ffma2(a01.x, bb1, acc[0][1]);
            acc[0][2] = ffma2(a01.x, bb2, acc[0][2]);
            acc[0][3] = ffma2(a01.x, bb3, acc[0][3]);
            acc[1][0] = ffma2(a01.y, bb0, acc[1][0]);
            acc[1][1] = ffma2(a01.y, bb1, acc[1][1]);
            acc[1][2] = ffma2(a01.y, bb2, acc[1][2]);
            acc[1][3] = ffma2(a01.y, bb3, acc[1][3]);
            acc[2][0] = ffma2(a23.x, bb0, acc[2][0]);
            acc[2][1] = ffma2(a23.x, bb1, acc[2][1]);
            acc[2][2] = ffma2(a23.x, bb2, acc[2][2]);
            acc[2][3] = ffma2(a23.x, bb3, acc[2][3]);
            acc[3][0] = ffma2(a23.y, bb0, acc[3][0]);
            acc[3][1] = ffma2(a23.y, bb1, acc[3][1]);
            acc[3][2] = ffma2(a23.y, bb2, acc[3][2]);
            acc[3][3] = ffma2(a23.y, bb3, acc[3][3]);
        }
        __syncthreads();
    }

    const int row = row0 + tx*4;
    const int b = row / 196, n = row - b*196;
    #pragma unroll
    for (int ip = 0; ip < 4; ip++) {
        float2 f0 = unpack2(acc[ip][0]);
        float2 f1 = unpack2(acc[ip][1]);
        float2 f2 = unpack2(acc[ip][2]);
        float2 f3 = unpack2(acc[ip][3]);
        int oA = o0 + ty*8 + ip*2;
        float biasA = g_bp[oA], biasB = g_bp[oA+1];
        float4 vA = make_float4(f0.x+biasA, f1.x+biasA, f2.x+biasA, f3.x+biasA);
        float4 vB = make_float4(f0.y+biasB, f1.y+biasB, f2.y+biasB, f3.y+biasB);
        *reinterpret_cast<float4*>(&out[b*50176 + oA*196 + n])     = vA;
        *reinterpret_cast<float4*>(&out[b*50176 + (oA+1)*196 + n]) = vB;
    }
}

// ---------------- launch ----------------------------------------------------
extern "C" void kernel_launch(void* const* d_in, const int* in_sizes, int n_in,
                              void* d_out, int out_size)
{
    const float* hs   = (const float*)d_in[0];
    const float* wq   = (const float*)d_in[1];
    const float* bq   = (const float*)d_in[2];
    const float* sq   = (const float*)d_in[3];
    const float* tq   = (const float*)d_in[4];
    const float* wk   = (const float*)d_in[5];
    const float* bk   = (const float*)d_in[6];
    const float* sk   = (const float*)d_in[7];
    const float* tk   = (const float*)d_in[8];
    const float* wv   = (const float*)d_in[9];
    const float* bv   = (const float*)d_in[10];
    const float* sv   = (const float*)d_in[11];
    const float* tv   = (const float*)d_in[12];
    const float* wvl  = (const float*)d_in[13];
    const float* bvl  = (const float*)d_in[14];
    const float* svl  = (const float*)d_in[15];
    const float* tvl  = (const float*)d_in[16];
    const float* th1  = (const float*)d_in[17];
    const float* bth1 = (const float*)d_in[18];
    const float* th2  = (const float*)d_in[19];
    const float* bth2 = (const float*)d_in[20];
    const float* wp   = (const float*)d_in[21];
    const float* bp   = (const float*)d_in[22];
    const float* sp   = (const float*)d_in[23];
    const float* tp   = (const float*)d_in[24];
    const float* ab   = (const float*)d_in[25];
    const int*   bidx = (const int*)d_in[26];

    cudaFuncSetAttribute(attn_kernel, cudaFuncAttributeMaxDynamicSharedMemorySize, 101888);

    const int pre_total = DIM_*QKV_ + DH_*DIM_ + QKV_ + 256 + H_*NOFF_;
    precompute_kernel<<<(pre_total + 255)/256, 256>>>(
        wq,bq,sq,tq, wk,bk,sk,tk, wv,bv,sv,tv, wp,bp,sp,tp, th1, ab);

    proj_kernel<<<dim3(392, 12), 256>>>(hs);
    dwconv_kernel<<<dim3(14, 128), 512>>>(wvl, bvl, svl, tvl);
    attn_kernel<<<dim3(28, 128), 512, 101888>>>(th1, bth1, th2, bth2, bidx);
    outproj_kernel<<<dim3(196, 4), 256>>>((float*)d_out);
}

// round 13
// speedup vs baseline: 1.5163x; 1.0083x over previous
#include <cuda_runtime.h>
#include <math.h>

// Problem constants
#define RES_ 14
#define N_ 196
#define B_ 128
#define DIM_ 256
#define H_ 8
#define KD_ 32
#define DV_ 128
#define DH_ 1024
#define NOFF_ 196
#define QKV_ 1536
#define SCALE_ 0.17677669529663687f

typedef unsigned long long ull;

// ---- packed fp32x2 helpers -------------------------------------------------
__device__ __forceinline__ ull ffma2(ull a, ull b, ull c) {
    ull d; asm("fma.rn.f32x2 %0, %1, %2, %3;" : "=l"(d) : "l"(a), "l"(b), "l"(c)); return d;
}
__device__ __forceinline__ ull fadd2(ull a, ull b) {
    ull d; asm("add.rn.f32x2 %0, %1, %2;" : "=l"(d) : "l"(a), "l"(b)); return d;
}
__device__ __forceinline__ ull fmul2(ull a, ull b) {
    ull d; asm("mul.rn.f32x2 %0, %1, %2;" : "=l"(d) : "l"(a), "l"(b)); return d;
}
__device__ __forceinline__ ull pack2(float lo, float hi) {
    ull d; asm("mov.b64 %0, {%1, %2};" : "=l"(d) : "f"(lo), "f"(hi)); return d;
}
__device__ __forceinline__ float2 unpack2(ull d) {
    float2 r; asm("mov.b64 {%0, %1}, %2;" : "=f"(r.x), "=f"(r.y) : "l"(d)); return r;
}

// ---------------- scratch (static device globals) --------------------------
__device__ __align__(16) float g_wall[DIM_*QKV_];
__device__ __align__(16) float g_ball[QKV_];
__device__ __align__(16) float g_wp[DH_*DIM_];
__device__ __align__(16) float g_bp[DIM_];
__device__ __align__(16) float g_abm[H_*NOFF_];
__device__ __align__(16) float g_q [B_*N_*256];     // (b,n,c)
// K paired layout: g_k[((b*128 + cp)*196 + m)*2 + par], cp=c/2, par=c&1
__device__ __align__(16) float g_k [B_*256*N_];
__device__ __align__(16) float g_v [B_*N_*DH_];     // (b,n,c) — for dwconv
// V interleaved: g_v2[((b*98+pm)*1024 + c0)*2 + {0..3}] = (c0_e, c0_o, c1_e, c1_o)
__device__ __align__(16) float g_v2[B_*N_*DH_];
__device__ __align__(16) float g_vl[B_*N_*DH_];
__device__ __align__(16) float g_ao[B_*N_*DH_];     // gelu(attn_out + vl)

// ---------------- kernel 0: fold scales / mix biases ------------------------
__global__ void precompute_kernel(
    const float* __restrict__ wq, const float* __restrict__ bq,
    const float* __restrict__ sq, const float* __restrict__ tq,
    const float* __restrict__ wk, const float* __restrict__ bk,
    const float* __restrict__ sk, const float* __restrict__ tk,
    const float* __restrict__ wv, const float* __restrict__ bv,
    const float* __restrict__ sv, const float* __restrict__ tv,
    const float* __restrict__ wp, const float* __restrict__ bp,
    const float* __restrict__ sp, const float* __restrict__ tp,
    const float* __restrict__ th1, const float* __restrict__ ab)
{
    int i = blockIdx.x * blockDim.x + threadIdx.x;
    if (i < DIM_*QKV_) {
        int c = i / QKV_, o = i % QKV_;
        float w;
        if (o < 256)       w = wq[c*256 + o]        * sq[o];
        else if (o < 512)  w = wk[c*256 + (o-256)]  * sk[o-256];
        else               w = wv[c*1024 + (o-512)] * sv[o-512];
        g_wall[i] = w;
        return;
    }
    int j = i - DIM_*QKV_;
    if (j < DH_*DIM_) {
        int c = j / 256, o = j % 256;
        g_wp[j] = wp[c*256 + o] * sp[o];
        return;
    }
    int l = j - DH_*DIM_;
    if (l < QKV_) {
        float v;
        if (l < 256)       v = bq[l]*sq[l] + tq[l];
        else if (l < 512)  v = bk[l-256]*sk[l-256] + tk[l-256];
        else               v = bv[l-512]*sv[l-512] + tv[l-512];
        g_ball[l] = v;
        return;
    }
    int m2 = l - QKV_;
    if (m2 < 256) { g_bp[m2] = bp[m2]*sp[m2] + tp[m2]; return; }
    int a = m2 - 256;
    if (a < H_*NOFF_) {
        int g = a / NOFF_, f = a % NOFF_;
        float s = 0.f;
        #pragma unroll
        for (int h = 0; h < 8; h++) s = fmaf(th1[g*8+h], ab[h*NOFF_ + f], s);
        g_abm[a] = s;
    }
}

// ---------------- kernel 1: fused QKV projection GEMM ----------------------
// 64x128 tile, double-buffered smem with register-staged prefetch.
// dyn smem layout (floats): [Xs0(2048) | Xs1(2048) | Ws0(4096) | Ws1(4096)]
__global__ __launch_bounds__(256, 2) void proj_kernel(const float* __restrict__ hs)
{
    extern __shared__ __align__(16) float sm[];
    const int tid = threadIdx.x;
    const int tx = tid & 31, ty = tid >> 5;
    const int rowBase = blockIdx.x * 64;
    const int bo = blockIdx.y * 128;

    int xbase[8];
    #pragma unroll
    for (int i = 0; i < 8; i++) {
        int idx = tid + i*256;
        int kk = idx >> 6, r = idx & 63;
        int row = rowBase + r;
        int b = row / 196, n = row - b*196;
        xbase[i] = b*50176 + kk*196 + n;
    }

    ull acc[4][4];
    #pragma unroll
    for (int i = 0; i < 4; i++)
        #pragma unroll
        for (int j = 0; j < 4; j++) acc[i][j] = 0ULL;

    // prologue: fill buffer 0 with tile 0
    #pragma unroll
    for (int i = 0; i < 8; i++) {
        int idx = tid + i*256;
        sm[(idx >> 6)*64 + (idx & 63)] = hs[xbase[i]];
    }
    #pragma unroll
    for (int i = 0; i < 16; i++) {
        int idx = tid + i*256;
        int kk = idx >> 7, oo = idx & 127;
        sm[4096 + kk*128 + oo] = g_wall[kk*1536 + bo + oo];
    }
    __syncthreads();

    int buf = 0;
    for (int t = 0; t < 8; t++) {
        float xr[8], wr[16];
        if (t < 7) {
            const int k0n = (t+1)*32;
            #pragma unroll
            for (int i = 0; i < 8; i++)
                xr[i] = hs[xbase[i] + k0n*196];
            #pragma unroll
            for (int i = 0; i < 16; i++) {
                int idx = tid + i*256;
                wr[i] = g_wall[(k0n + (idx >> 7))*1536 + bo + (idx & 127)];
            }
        }

        const float* Xs = sm + buf*2048;
        const float* Ws = sm + 4096 + buf*4096;
        #pragma unroll
        for (int kk = 0; kk < 32; kk++) {
            ulonglong2 a01 = *reinterpret_cast<const ulonglong2*>(&Xs[kk*64 + ty*8]);
            ulonglong2 a23 = *reinterpret_cast<const ulonglong2*>(&Xs[kk*64 + ty*8 + 4]);
            float4 b4 = *reinterpret_cast<const float4*>(&Ws[kk*128 + tx*4]);
            ull bb0 = pack2(b4.x, b4.x), bb1 = pack2(b4.y, b4.y);
            ull bb2 = pack2(b4.z, b4.z), bb3 = pack2(b4.w, b4.w);
            acc[0][0] = ffma2(a01.x, bb0, acc[0][0]);
            acc[0][1] = ffma2(a01.x, bb1, acc[0][1]);
            acc[0][2] = ffma2(a01.x, bb2, acc[0][2]);
            acc[0][3] = ffma2(a01.x, bb3, acc[0][3]);
            acc[1][0] = ffma2(a01.y, bb0, acc[1][0]);
            acc[1][1] = ffma2(a01.y, bb1, acc[1][1]);
            acc[1][2] = ffma2(a01.y, bb2, acc[1][2]);
            acc[1][3] = ffma2(a01.y, bb3, acc[1][3]);
            acc[2][0] = ffma2(a23.x, bb0, acc[2][0]);
            acc[2][1] = ffma2(a23.x, bb1, acc[2][1]);
            acc[2][2] = ffma2(a23.x, bb2, acc[2][2]);
            acc[2][3] = ffma2(a23.x, bb3, acc[2][3]);
            acc[3][0] = ffma2(a23.y, bb0, acc[3][0]);
            acc[3][1] = ffma2(a23.y, bb1, acc[3][1]);
            acc[3][2] = ffma2(a23.y, bb2, acc[3][2]);
            acc[3][3] = ffma2(a23.y, bb3, acc[3][3]);
        }

        if (t < 7) {
            float* Xn = sm + (buf^1)*2048;
            float* Wn = sm + 4096 + (buf^1)*4096;
            #pragma unroll
            for (int i = 0; i < 8; i++) {
                int idx = tid + i*256;
                Xn[(idx >> 6)*64 + (idx & 63)] = xr[i];
            }
            #pragma unroll
            for (int i = 0; i < 16; i++) {
                int idx = tid + i*256;
                Wn[(idx >> 7)*128 + (idx & 127)] = wr[i];
            }
        }
        __syncthreads();
        buf ^= 1;
    }

    const int o4 = bo + tx*4;
    const float4 bia = *reinterpret_cast<const float4*>(&g_ball[o4]);
    #pragma unroll
    for (int ip = 0; ip < 4; ip++) {
        float2 f0 = unpack2(acc[ip][0]);
        float2 f1 = unpack2(acc[ip][1]);
        float2 f2 = unpack2(acc[ip][2]);
        float2 f3 = unpack2(acc[ip][3]);
        int r0 = rowBase + ty*8 + ip*2;     // always even
        float4 v0 = make_float4(f0.x+bia.x, f1.x+bia.y, f2.x+bia.z, f3.x+bia.w);
        float4 v1 = make_float4(f0.y+bia.x, f1.y+bia.y, f2.y+bia.z, f3.y+bia.w);
        if (bo < 256) {
            *reinterpret_cast<float4*>(&g_q[r0*256 + o4])     = v0;
            *reinterpret_cast<float4*>(&g_q[(r0+1)*256 + o4]) = v1;
        } else if (bo < 512) {
            const int cp0 = (o4 - 256) >> 1;   // even
            #pragma unroll
            for (int lane = 0; lane < 2; lane++) {
                int row = r0 + lane;
                int b = row / 196, n = row - b*196;
                float2 p0 = (lane == 0) ? make_float2(v0.x, v0.y) : make_float2(v1.x, v1.y);
                float2 p1 = (lane == 0) ? make_float2(v0.z, v0.w) : make_float2(v1.z, v1.w);
                *reinterpret_cast<float2*>(&g_k[((b*128 + cp0)*196 + n)*2])     = p0;
                *reinterpret_cast<float2*>(&g_k[((b*128 + cp0 + 1)*196 + n)*2]) = p1;
            }
        } else {
            *reinterpret_cast<float4*>(&g_v[r0*1024 + o4-512])     = v0;
            *reinterpret_cast<float4*>(&g_v[(r0+1)*1024 + o4-512]) = v1;
            int b = r0 / 196, n = r0 - b*196, pm = n >> 1;
            float4 qA = make_float4(v0.x, v1.x, v0.y, v1.y);
            float4 qB = make_float4(v0.z, v1.z, v0.w, v1.w);
            float* vb2 = &g_v2[(((size_t)b*98 + pm)*1024 + (o4-512))*2];
            *reinterpret_cast<float4*>(vb2)     = qA;
            *reinterpret_cast<float4*>(vb2 + 4) = qB;
        }
    }
}

// ---------------- kernel 2: depthwise 3x3 conv, sliding window over x ------
__global__ __launch_bounds__(512) void dwconv_kernel(
    const float* __restrict__ wvl, const float* __restrict__ bvl,
    const float* __restrict__ svl, const float* __restrict__ tvl)
{
    const int b = blockIdx.y, y = blockIdx.x;
    const int c0 = threadIdx.x * 2;

    ull wt[9];
    #pragma unroll
    for (int k = 0; k < 9; k++) wt[k] = pack2(wvl[c0*9 + k], wvl[c0*9 + 9 + k]);
    float2 bv2 = make_float2(bvl[c0], bvl[c0+1]);
    float2 sv2 = make_float2(svl[c0], svl[c0+1]);
    float2 tv2 = make_float2(tvl[c0], tvl[c0+1]);

    const float* vbase = &g_v[(b*196)*1024 + c0];
    const bool rok0 = (y > 0), rok2 = (y < 13);
    const int r0off = (y-1)*14*1024, r1off = y*14*1024, r2off = (y+1)*14*1024;

    ull win[3][3];
    #pragma unroll
    for (int r = 0; r < 3; r++) win[r][0] = 0ULL;
    win[0][1] = rok0 ? *(const ull*)&vbase[r0off] : 0ULL;
    win[1][1] =        *(const ull*)&vbase[r1off];
    win[2][1] = rok2 ? *(const ull*)&vbase[r2off] : 0ULL;
    win[0][2] = rok0 ? *(const ull*)&vbase[r0off + 1024] : 0ULL;
    win[1][2] =        *(const ull*)&vbase[r1off + 1024];
    win[2][2] = rok2 ? *(const ull*)&vbase[r2off + 1024] : 0ULL;

    #pragma unroll
    for (int x = 0; x < 14; x++) {
        ull acc = 0ULL;
        #pragma unroll
        for (int r = 0; r < 3; r++)
            #pragma unroll
            for (int j = 0; j < 3; j++)
                acc = ffma2(win[r][j], wt[r*3 + j], acc);
        float2 f = unpack2(acc);
        float2 o;
        o.x = fmaf(f.x + bv2.x, sv2.x, tv2.x);
        o.y = fmaf(f.y + bv2.y, sv2.y, tv2.y);
        *reinterpret_cast<float2*>(&g_vl[(b*196 + y*14 + x)*1024 + c0]) = o;

        #pragma unroll
        for (int r = 0; r < 3; r++) { win[r][0] = win[r][1]; win[r][1] = win[r][2]; }
        if (x < 12) {
            int xo = (x+2)*1024;
            win[0][2] = rok0 ? *(const ull*)&vbase[r0off + xo] : 0ULL;
            win[1][2] =        *(const ull*)&vbase[r1off + xo];
            win[2][2] = rok2 ? *(const ull*)&vbase[r2off + xo] : 0ULL;
        } else {
            win[0][2] = 0ULL; win[1][2] = 0ULL; win[2][2] = 0ULL;
        }
    }
}

// ---------------- kernel 3: fused attention (512 thr, 7 q-rows, ping-pong) -
__global__ __launch_bounds__(512, 2) void attn_kernel(
    const float* __restrict__ th1, const float* __restrict__ bth1,
    const float* __restrict__ th2, const float* __restrict__ bth2,
    const int*   __restrict__ idxs)
{
    extern __shared__ __align__(16) float smem[];
    float* qs   = smem;             // 1792
    float* a3   = smem + 1792;      // 10976 raw logits / th2-mixed probs
    float* a2   = smem + 12768;     // 10976 th1-mixed logits / softmax probs
    float* abms = smem + 23744;     // 1568
    float* th1s = smem + 25312;     // 64 (pre-scaled)
    float* th2s = smem + 25376;     // 64
    float* bts  = smem + 25440;     // 16
    ull*   bt2u = reinterpret_cast<ull*>(smem + 25456);  // 8 ull

    const int tid = threadIdx.x;
    const int b  = blockIdx.y;
    const int n0 = blockIdx.x * 7;

    for (int idx = tid; idx < 1792; idx += 512)
        qs[idx] = g_q[(b*196 + n0 + (idx >> 8))*256 + (idx & 255)];
    for (int idx = tid; idx < 1568; idx += 512)
        abms[idx] = g_abm[idx];
    if (tid < 64) { th1s[tid] = th1[tid] * SCALE_; th2s[tid] = th2[tid]; }
    if (tid < 8)  { bts[tid] = bth1[tid]; bts[8 + tid] = bth2[tid];
                    bt2u[tid] = pack2(bth2[tid], bth2[tid]); }
    __syncthreads();

    // ---- phase 1: raw logits -> a3. item = (m, h), all 512 threads --------
    for (int it = tid; it < 1568; it += 512) {
        const int h = it / 196;
        const int m = it - h*196;
        // paired-K: base of pair cp = h*16, element (m, parity)
        const float* kb = &g_k[((b*128 + h*16)*196 + m)*2];
        ull s2[7];
        #pragma unroll
        for (int n = 0; n < 7; n++) s2[n] = 0ULL;
        #pragma unroll
        for (int c8 = 0; c8 < 8; c8++) {
            ull k01 = *reinterpret_cast<const ull*>(kb + c8*784);
            ull k23 = *reinterpret_cast<const ull*>(kb + c8*784 + 392);
            #pragma unroll
            for (int n = 0; n < 7; n++) {
                ulonglong2 q2 = *reinterpret_cast<const ulonglong2*>(&qs[n*256 + h*32 + c8*4]);
                s2[n] = ffma2(q2.x, k01, ffma2(q2.y, k23, s2[n]));
            }
        }
        #pragma unroll
        for (int n = 0; n < 7; n++) {
            float2 f = unpack2(s2[n]);
            a3[(n*8 + h)*196 + m] = f.x + f.y;
        }
    }
    __syncthreads();

    // ---- phase 1b: th1 mix + bias + ab : a3 -> a2 --------------------------
    {
        const int gp = tid >> 7;
        const int g0 = gp*2;
        ull wd0[8], wd1[8];
        #pragma unroll
        for (int h = 0; h < 8; h++) {
            float w0 = th1s[g0*8 + h], w1 = th1s[g0*8 + 8 + h];
            wd0[h] = pack2(w0, w0); wd1[h] = pack2(w1, w1);
        }
        const float bt0 = bts[g0], bt1 = bts[g0+1];
        const ull* a3u = reinterpret_cast<const ull*>(a3);
        ull* a2u = reinterpret_cast<ull*>(a2);
        for (int it = (tid & 127); it < 686; it += 128) {
            const int n = it / 98;
            const int pm = it - n*98;
            const int m0 = pm*2;
            int2 ixp = *reinterpret_cast<const int2*>(&idxs[(n0+n)*196 + m0]);
            ull t0 = pack2(bt0 + abms[g0*196 + ixp.x],     bt0 + abms[g0*196 + ixp.y]);
            ull t1 = pack2(bt1 + abms[(g0+1)*196 + ixp.x], bt1 + abms[(g0+1)*196 + ixp.y]);
            const ull* pb = a3u + n*784 + pm;
            #pragma unroll
            for (int h = 0; h < 8; h++) {
                ull p2 = pb[h*98];
                t0 = ffma2(p2, wd0[h], t0);
                t1 = ffma2(p2, wd1[h], t1);
            }
            a2u[(n*8 + g0)*98 + pm]     = t0;
            a2u[(n*8 + g0 + 1)*98 + pm] = t1;
        }
    }
    __syncthreads();

    // ---- phase 2: softmax on a2 (paired) -----------------------------------
    {
        const int w = tid >> 5, lane = tid & 31;
        for (int r = w; r < 56; r += 16) {
            ull* rowu = reinterpret_cast<ull*>(a2 + r*196);
            float mx = -1e30f;
            for (int i = lane; i < 98; i += 32) {
                float2 f = unpack2(rowu[i]);
                mx = fmaxf(mx, fmaxf(f.x, f.y));
            }
            #pragma unroll
            for (int off = 16; off > 0; off >>= 1)
                mx = fmaxf(mx, __shfl_xor_sync(0xffffffffu, mx, off));
            ull sm2 = 0ULL;
            for (int i = lane; i < 98; i += 32) {
                float2 f = unpack2(rowu[i]);
                f.x = __expf(f.x - mx); f.y = __expf(f.y - mx);
                ull e = pack2(f.x, f.y);
                rowu[i] = e;
                sm2 = fadd2(sm2, e);
            }
            float2 fs = unpack2(sm2);
            float sm = fs.x + fs.y;
            #pragma unroll
            for (int off = 16; off > 0; off >>= 1)
                sm += __shfl_xor_sync(0xffffffffu, sm, off);
            float inv = 1.f / sm;
            ull inv2 = pack2(inv, inv);
            for (int i = lane; i < 98; i += 32) rowu[i] = fmul2(rowu[i], inv2);
        }
    }
    __syncthreads();

    // ---- phase 3: th2 mix + bias : a2 -> a3 --------------------------------
    {
        const int gp = tid >> 7;
        const int g0 = gp*2;
        ull wd0[8], wd1[8];
        #pragma unroll
        for (int h = 0; h < 8; h++) {
            float w0 = th2s[g0*8 + h], w1 = th2s[g0*8 + 8 + h];
            wd0[h] = pack2(w0, w0); wd1[h] = pack2(w1, w1);
        }
        const ull bt0 = bt2u[g0], bt1 = bt2u[g0+1];
        const ull* a2u = reinterpret_cast<const ull*>(a2);
        ull* a3u = reinterpret_cast<ull*>(a3);
        for (int it = (tid & 127); it < 686; it += 128) {
            const int n = it / 98;
            const int pm = it - n*98;
            ull t0 = bt0, t1 = bt1;
            const ull* pb = a2u + n*784 + pm;
            #pragma unroll
            for (int h = 0; h < 8; h++) {
                ull p2 = pb[h*98];
                t0 = ffma2(p2, wd0[h], t0);
                t1 = ffma2(p2, wd1[h], t1);
            }
            a3u[(n*8 + g0)*98 + pm]     = t0;
            a3u[(n*8 + g0 + 1)*98 + pm] = t1;
        }
    }
    __syncthreads();

    // ---- phase 4: attn @ V + vl add + exact gelu ---------------------------
    // g_v2 delivers (c0_e, c0_o, c1_e, c1_o) per LDG.128 — zero packing MOVs.
    {
        const int head = tid >> 6;
        const int c0 = head*128 + (tid & 63)*2;
        ull accA[7], accB[7];
        #pragma unroll
        for (int n = 0; n < 7; n++) { accA[n] = 0ULL; accB[n] = 0ULL; }

        const ull* pbase = reinterpret_cast<const ull*>(a3) + head*98;
        const float* vb2 = &g_v2[((size_t)(b*98)*1024 + c0)*2];
        #pragma unroll 7
        for (int pm = 0; pm < 98; pm++) {
            ulonglong2 vv = *reinterpret_cast<const ulonglong2*>(vb2 + (size_t)pm*2048);
            #pragma unroll
            for (int n = 0; n < 7; n++) {
                ull p = pbase[n*784 + pm];
                accA[n] = ffma2(p, vv.x, accA[n]);
                accB[n] = ffma2(p, vv.y, accB[n]);
            }
        }
        #pragma unroll
        for (int n = 0; n < 7; n++) {
            int off = (b*196 + n0 + n)*1024 + c0;
            float2 vl2 = *reinterpret_cast<const float2*>(&g_vl[off]);
            float2 fA = unpack2(accA[n]);
            float2 fB = unpack2(accB[n]);
            float a0 = fA.x + fA.y + vl2.x;
            float a1 = fB.x + fB.y + vl2.y;
            float2 o2;
            o2.x = 0.5f * a0 * (1.f + erff(a0 * 0.7071067811865476f));
            o2.y = 0.5f * a1 * (1.f + erff(a1 * 0.7071067811865476f));
            *reinterpret_cast<float2*>(&g_ao[off]) = o2;
        }
    }
}

// ---------------- kernel 4: output projection GEMM -------------------------
// 64o x 128row tile, k=1024, double-buffered smem with register prefetch.
// dyn smem layout (floats): [As0(2048) | As1(2048) | Bs0(4224) | Bs1(4224)]
__global__ __launch_bounds__(256, 2) void outproj_kernel(float* __restrict__ out)
{
    extern __shared__ __align__(16) float sm[];
    const int tid = threadIdx.x;
    const int tx = tid & 31, ty = tid >> 5;
    const int row0 = blockIdx.x * 128;
    const int o0 = blockIdx.y * 64;

    const int kk4 = (tid & 7) * 4;
    const int rb = tid >> 3;

    ull acc[4][4];
    #pragma unroll
    for (int i = 0; i < 4; i++)
        #pragma unroll
        for (int j = 0; j < 4; j++) acc[i][j] = 0ULL;

    // prologue: fill buffer 0 with k-tile 0
    #pragma unroll
    for (int i = 0; i < 8; i++) {
        int idx = tid + i*256;
        sm[(idx >> 6)*64 + (idx & 63)] = g_wp[(idx >> 6)*256 + o0 + (idx & 63)];
    }
    #pragma unroll
    for (int i = 0; i < 4; i++) {
        int r = rb + i*32;
        float4 x4 = *reinterpret_cast<const float4*>(&g_ao[(row0+r)*1024 + kk4]);
        float* Bs = sm + 4096;
        Bs[(kk4+0)*132 + r] = x4.x; Bs[(kk4+1)*132 + r] = x4.y;
        Bs[(kk4+2)*132 + r] = x4.z; Bs[(kk4+3)*132 + r] = x4.w;
    }
    __syncthreads();

    int buf = 0;
    for (int t = 0; t < 32; t++) {
        float ar[8];
        float4 br[4];
        if (t < 31) {
            const int k0n = (t+1)*32;
            #pragma unroll
            for (int i = 0; i < 8; i++) {
                int idx = tid + i*256;
                ar[i] = g_wp[(k0n + (idx >> 6))*256 + o0 + (idx & 63)];
            }
            #pragma unroll
            for (int i = 0; i < 4; i++) {
                int r = rb + i*32;
                br[i] = *reinterpret_cast<const float4*>(&g_ao[(row0+r)*1024 + k0n + kk4]);
            }
        }

        const float* As = sm + buf*2048;
        const float* Bs = sm + 4096 + buf*4224;
        #pragma unroll
        for (int kk = 0; kk < 32; kk++) {
            ulonglong2 a01 = *reinterpret_cast<const ulonglong2*>(&As[kk*64 + ty*8]);
            ulonglong2 a23 = *reinterpret_cast<const ulonglong2*>(&As[kk*64 + ty*8 + 4]);
            float4 b4 = *reinterpret_cast<const float4*>(&Bs[kk*132 + tx*4]);
            ull bb0 = pack2(b4.x, b4.x), bb1 = pack2(b4.y, b4.y);
            ull bb2 = pack2(b4.z, b4.z), bb3 = pack2(b4.w, b4.w);
            acc[0][0] = ffma2(a01.x, bb0, acc[0][0]);
            acc[0][1] = ffma2(a01.x, bb1, acc[0][1]);
            acc[0][2] = ffma2(a01.x, bb2, acc[0][2]);
            acc[0][3] = ffma2(a01.x, bb3, acc[0][3]);
            acc[1][0] = ffma2(a01.y, bb0, acc[1][0]);
            acc[1][1] = ffma2(a01.y, bb1, acc[1][1]);
            acc[1][2] = ffma2(a01.y, bb2, acc[1][2]);
            acc[1][3] = ffma2(a01.y, bb3, acc[1][3]);
            acc[2][0] = ffma2(a23.x, bb0, acc[2][0]);
            acc[2][1] = ffma2(a23.x, bb1, acc[2][1]);
            acc[2][2] = ffma2(a23.x, bb2, acc[2][2]);
            acc[2][3] = ffma2(a23.x, bb3, acc[2][3]);
            acc[3][0] = ffma2(a23.y, bb0, acc[3][0]);
            acc[3][1] = ffma2(a23.y, bb1, acc[3][1]);
            acc[3][2] = ffma2(a23.y, bb2, acc[3][2]);
            acc[3][3] = ffma2(a23.y, bb3, acc[3][3]);
        }

        if (t < 31) {
            float* An = sm + (buf^1)*2048;
            float* Bn = sm + 4096 + (buf^1)*4224;
            #pragma unroll
            for (int i = 0; i < 8; i++) {
                int idx = tid + i*256;
                An[(idx >> 6)*64 + (idx & 63)] = ar[i];
            }
            #pragma unroll
            for (int i = 0; i < 4; i++) {
                int r = rb + i*32;
                Bn[(kk4+0)*132 + r] = br[i].x; Bn[(kk4+1)*132 + r] = br[i].y;
                Bn[(kk4+2)*132 + r] = br[i].z; Bn[(kk4+3)*132 + r] = br[i].w;
            }
        }
        __syncthreads();
        buf ^= 1;
    }

    const int row = row0 + tx*4;
    const int b = row / 196, n = row - b*196;
    #pragma unroll
    for (int ip = 0; ip < 4; ip++) {
        float2 f0 = unpack2(acc[ip][0]);
        float2 f1 = unpack2(acc[ip][1]);
        float2 f2 = unpack2(acc[ip][2]);
        float2 f3 = unpack2(acc[ip][3]);
        int oA = o0 + ty*8 + ip*2;
        float biasA = g_bp[oA], biasB = g_bp[oA+1];
        float4 vA = make_float4(f0.x+biasA, f1.x+biasA, f2.x+biasA, f3.x+biasA);
        float4 vB = make_float4(f0.y+biasB, f1.y+biasB, f2.y+biasB, f3.y+biasB);
        *reinterpret_cast<float4*>(&out[b*50176 + oA*196 + n])     = vA;
        *reinterpret_cast<float4*>(&out[b*50176 + (oA+1)*196 + n]) = vB;
    }
}

// ---------------- launch ----------------------------------------------------
extern "C" void kernel_launch(void* const* d_in, const int* in_sizes, int n_in,
                              void* d_out, int out_size)
{
    const float* hs   = (const float*)d_in[0];
    const float* wq   = (const float*)d_in[1];
    const float* bq   = (const float*)d_in[2];
    const float* sq   = (const float*)d_in[3];
    const float* tq   = (const float*)d_in[4];
    const float* wk   = (const float*)d_in[5];
    const float* bk   = (const float*)d_in[6];
    const float* sk   = (const float*)d_in[7];
    const float* tk   = (const float*)d_in[8];
    const float* wv   = (const float*)d_in[9];
    const float* bv   = (const float*)d_in[10];
    const float* sv   = (const float*)d_in[11];
    const float* tv   = (const float*)d_in[12];
    const float* wvl  = (const float*)d_in[13];
    const float* bvl  = (const float*)d_in[14];
    const float* svl  = (const float*)d_in[15];
    const float* tvl  = (const float*)d_in[16];
    const float* th1  = (const float*)d_in[17];
    const float* bth1 = (const float*)d_in[18];
    const float* th2  = (const float*)d_in[19];
    const float* bth2 = (const float*)d_in[20];
    const float* wp   = (const float*)d_in[21];
    const float* bp   = (const float*)d_in[22];
    const float* sp   = (const float*)d_in[23];
    const float* tp   = (const float*)d_in[24];
    const float* ab   = (const float*)d_in[25];
    const int*   bidx = (const int*)d_in[26];

    cudaFuncSetAttribute(attn_kernel,    cudaFuncAttributeMaxDynamicSharedMemorySize, 101888);
    cudaFuncSetAttribute(proj_kernel,    cudaFuncAttributeMaxDynamicSharedMemorySize, 49152);
    cudaFuncSetAttribute(outproj_kernel, cudaFuncAttributeMaxDynamicSharedMemorySize, 50176);

    const int pre_total = DIM_*QKV_ + DH_*DIM_ + QKV_ + 256 + H_*NOFF_;
    precompute_kernel<<<(pre_total + 255)/256, 256>>>(
        wq,bq,sq,tq, wk,bk,sk,tk, wv,bv,sv,tv, wp,bp,sp,tp, th1, ab);

    proj_kernel<<<dim3(392, 12), 256, 49152>>>(hs);
    dwconv_kernel<<<dim3(14, 128), 512>>>(wvl, bvl, svl, tvl);
    attn_kernel<<<dim3(28, 128), 512, 101888>>>(th1, bth1, th2, bth2, bidx);
    outproj_kernel<<<dim3(196, 4), 256, 50176>>>((float*)d_out);
}

// round 14
// speedup vs baseline: 1.5825x; 1.0437x over previous
#include <cuda_runtime.h>
#include <math.h>

// Problem constants
#define RES_ 14
#define N_ 196
#define B_ 128
#define DIM_ 256
#define H_ 8
#define KD_ 32
#define DV_ 128
#define DH_ 1024
#define NOFF_ 196
#define QKV_ 1536
#define SCALE_ 0.17677669529663687f

typedef unsigned long long ull;

// ---- packed fp32x2 helpers -------------------------------------------------
__device__ __forceinline__ ull ffma2(ull a, ull b, ull c) {
    ull d; asm("fma.rn.f32x2 %0, %1, %2, %3;" : "=l"(d) : "l"(a), "l"(b), "l"(c)); return d;
}
__device__ __forceinline__ ull fadd2(ull a, ull b) {
    ull d; asm("add.rn.f32x2 %0, %1, %2;" : "=l"(d) : "l"(a), "l"(b)); return d;
}
__device__ __forceinline__ ull fmul2(ull a, ull b) {
    ull d; asm("mul.rn.f32x2 %0, %1, %2;" : "=l"(d) : "l"(a), "l"(b)); return d;
}
__device__ __forceinline__ ull pack2(float lo, float hi) {
    ull d; asm("mov.b64 %0, {%1, %2};" : "=l"(d) : "f"(lo), "f"(hi)); return d;
}
__device__ __forceinline__ float2 unpack2(ull d) {
    float2 r; asm("mov.b64 {%0, %1}, %2;" : "=f"(r.x), "=f"(r.y) : "l"(d)); return r;
}

// ---------------- scratch (static device globals) --------------------------
__device__ __align__(16) float g_wall[DIM_*QKV_];
__device__ __align__(16) float g_ball[QKV_];
__device__ __align__(16) float g_wp[DH_*DIM_];
__device__ __align__(16) float g_bp[DIM_];
__device__ __align__(16) float g_abm[H_*NOFF_];
__device__ __align__(16) float g_q [B_*N_*256];     // (b,n,c)
// K paired layout: g_k[((b*128 + cp)*196 + m)*2 + par], cp=c/2, par=c&1
__device__ __align__(16) float g_k [B_*256*N_];
__device__ __align__(16) float g_v [B_*N_*DH_];     // (b,n,c) — for dwconv
// V interleaved: g_v2[((b*98+pm)*1024 + c0)*2 + {0..3}] = (c0_e, c0_o, c1_e, c1_o)
__device__ __align__(16) float g_v2[B_*N_*DH_];
__device__ __align__(16) float g_vl[B_*N_*DH_];
__device__ __align__(16) float g_ao[B_*N_*DH_];     // gelu(attn_out + vl)

// ---------------- kernel 0: fold scales / mix biases ------------------------
__global__ void precompute_kernel(
    const float* __restrict__ wq, const float* __restrict__ bq,
    const float* __restrict__ sq, const float* __restrict__ tq,
    const float* __restrict__ wk, const float* __restrict__ bk,
    const float* __restrict__ sk, const float* __restrict__ tk,
    const float* __restrict__ wv, const float* __restrict__ bv,
    const float* __restrict__ sv, const float* __restrict__ tv,
    const float* __restrict__ wp, const float* __restrict__ bp,
    const float* __restrict__ sp, const float* __restrict__ tp,
    const float* __restrict__ th1, const float* __restrict__ ab)
{
    int i = blockIdx.x * blockDim.x + threadIdx.x;
    if (i < DIM_*QKV_) {
        int c = i / QKV_, o = i % QKV_;
        float w;
        if (o < 256)       w = wq[c*256 + o]        * sq[o];
        else if (o < 512)  w = wk[c*256 + (o-256)]  * sk[o-256];
        else               w = wv[c*1024 + (o-512)] * sv[o-512];
        g_wall[i] = w;
        return;
    }
    int j = i - DIM_*QKV_;
    if (j < DH_*DIM_) {
        int c = j / 256, o = j % 256;
        g_wp[j] = wp[c*256 + o] * sp[o];
        return;
    }
    int l = j - DH_*DIM_;
    if (l < QKV_) {
        float v;
        if (l < 256)       v = bq[l]*sq[l] + tq[l];
        else if (l < 512)  v = bk[l-256]*sk[l-256] + tk[l-256];
        else               v = bv[l-512]*sv[l-512] + tv[l-512];
        g_ball[l] = v;
        return;
    }
    int m2 = l - QKV_;
    if (m2 < 256) { g_bp[m2] = bp[m2]*sp[m2] + tp[m2]; return; }
    int a = m2 - 256;
    if (a < H_*NOFF_) {
        int g = a / NOFF_, f = a % NOFF_;
        float s = 0.f;
        #pragma unroll
        for (int h = 0; h < 8; h++) s = fmaf(th1[g*8+h], ab[h*NOFF_ + f], s);
        g_abm[a] = s;
    }
}

// ---------------- kernel 1: fused QKV projection GEMM (64x128 tile) --------
__global__ __launch_bounds__(256, 2) void proj_kernel(const float* __restrict__ hs)
{
    __shared__ __align__(16) float Xs[32][64];
    __shared__ __align__(16) float Ws[32][128];
    const int tid = threadIdx.x;
    const int tx = tid & 31, ty = tid >> 5;
    const int rowBase = blockIdx.x * 64;
    const int bo = blockIdx.y * 128;

    int xbase[8];
    #pragma unroll
    for (int i = 0; i < 8; i++) {
        int idx = tid + i*256;
        int kk = idx >> 6, r = idx & 63;
        int row = rowBase + r;
        int b = row / 196, n = row - b*196;
        xbase[i] = b*50176 + kk*196 + n;
    }

    ull acc[4][4];
    #pragma unroll
    for (int i = 0; i < 4; i++)
        #pragma unroll
        for (int j = 0; j < 4; j++) acc[i][j] = 0ULL;

    for (int k0 = 0; k0 < 256; k0 += 32) {
        #pragma unroll
        for (int i = 0; i < 8; i++) {
            int idx = tid + i*256;
            int kk = idx >> 6, r = idx & 63;
            Xs[kk][r] = hs[xbase[i] + k0*196];
        }
        #pragma unroll
        for (int i = 0; i < 16; i++) {
            int idx = tid + i*256;
            int kk = idx >> 7, oo = idx & 127;
            Ws[kk][oo] = g_wall[(k0+kk)*1536 + bo + oo];
        }
        __syncthreads();
        #pragma unroll
        for (int kk = 0; kk < 32; kk++) {
            ulonglong2 a01 = *reinterpret_cast<const ulonglong2*>(&Xs[kk][ty*8]);
            ulonglong2 a23 = *reinterpret_cast<const ulonglong2*>(&Xs[kk][ty*8+4]);
            float4 b4 = *reinterpret_cast<const float4*>(&Ws[kk][tx*4]);
            ull bb0 = pack2(b4.x, b4.x), bb1 = pack2(b4.y, b4.y);
            ull bb2 = pack2(b4.z, b4.z), bb3 = pack2(b4.w, b4.w);
            acc[0][0] = ffma2(a01.x, bb0, acc[0][0]);
            acc[0][1] = ffma2(a01.x, bb1, acc[0][1]);
            acc[0][2] = ffma2(a01.x, bb2, acc[0][2]);
            acc[0][3] = ffma2(a01.x, bb3, acc[0][3]);
            acc[1][0] = ffma2(a01.y, bb0, acc[1][0]);
            acc[1][1] = ffma2(a01.y, bb1, acc[1][1]);
            acc[1][2] = ffma2(a01.y, bb2, acc[1][2]);
            acc[1][3] = ffma2(a01.y, bb3, acc[1][3]);
            acc[2][0] = ffma2(a23.x, bb0, acc[2][0]);
            acc[2][1] = ffma2(a23.x, bb1, acc[2][1]);
            acc[2][2] = ffma2(a23.x, bb2, acc[2][2]);
            acc[2][3] = ffma2(a23.x, bb3, acc[2][3]);
            acc[3][0] = ffma2(a23.y, bb0, acc[3][0]);
            acc[3][1] = ffma2(a23.y, bb1, acc[3][1]);
            acc[3][2] = ffma2(a23.y, bb2, acc[3][2]);
            acc[3][3] = ffma2(a23.y, bb3, acc[3][3]);
        }
        __syncthreads();
    }

    const int o4 = bo + tx*4;
    const float4 bia = *reinterpret_cast<const float4*>(&g_ball[o4]);
    #pragma unroll
    for (int ip = 0; ip < 4; ip++) {
        float2 f0 = unpack2(acc[ip][0]);
        float2 f1 = unpack2(acc[ip][1]);
        float2 f2 = unpack2(acc[ip][2]);
        float2 f3 = unpack2(acc[ip][3]);
        int r0 = rowBase + ty*8 + ip*2;     // always even
        float4 v0 = make_float4(f0.x+bia.x, f1.x+bia.y, f2.x+bia.z, f3.x+bia.w);
        float4 v1 = make_float4(f0.y+bia.x, f1.y+bia.y, f2.y+bia.z, f3.y+bia.w);
        if (bo < 256) {
            *reinterpret_cast<float4*>(&g_q[r0*256 + o4])     = v0;
            *reinterpret_cast<float4*>(&g_q[(r0+1)*256 + o4]) = v1;
        } else if (bo < 512) {
            // K paired layout: pair cp gets (c even, c odd) adjacent per m
            const int cp0 = (o4 - 256) >> 1;   // even
            #pragma unroll
            for (int lane = 0; lane < 2; lane++) {
                int row = r0 + lane;
                int b = row / 196, n = row - b*196;
                float2 p0 = (lane == 0) ? make_float2(v0.x, v0.y) : make_float2(v1.x, v1.y);
                float2 p1 = (lane == 0) ? make_float2(v0.z, v0.w) : make_float2(v1.z, v1.w);
                *reinterpret_cast<float2*>(&g_k[((b*128 + cp0)*196 + n)*2])     = p0;
                *reinterpret_cast<float2*>(&g_k[((b*128 + cp0 + 1)*196 + n)*2]) = p1;
            }
        } else {
            *reinterpret_cast<float4*>(&g_v[r0*1024 + o4-512])     = v0;
            *reinterpret_cast<float4*>(&g_v[(r0+1)*1024 + o4-512]) = v1;
            // interleaved copy for attn phase 4
            int b = r0 / 196, n = r0 - b*196, pm = n >> 1;
            float4 qA = make_float4(v0.x, v1.x, v0.y, v1.y);
            float4 qB = make_float4(v0.z, v1.z, v0.w, v1.w);
            float* vb2 = &g_v2[(((size_t)b*98 + pm)*1024 + (o4-512))*2];
            *reinterpret_cast<float4*>(vb2)     = qA;
            *reinterpret_cast<float4*>(vb2 + 4) = qB;
        }
    }
}

// ---------------- kernel 2: depthwise 3x3 conv, 2 output rows per block ----
__global__ __launch_bounds__(512) void dwconv_kernel(
    const float* __restrict__ wvl, const float* __restrict__ bvl,
    const float* __restrict__ svl, const float* __restrict__ tvl)
{
    const int b = blockIdx.y;
    const int y0 = blockIdx.x * 2, y1 = y0 + 1;
    const int c0 = threadIdx.x * 2;

    ull wt[9];
    #pragma unroll
    for (int k = 0; k < 9; k++) wt[k] = pack2(wvl[c0*9 + k], wvl[c0*9 + 9 + k]);
    float2 bv2 = make_float2(bvl[c0], bvl[c0+1]);
    float2 sv2 = make_float2(svl[c0], svl[c0+1]);
    float2 tv2 = make_float2(tvl[c0], tvl[c0+1]);

    const float* vbase = &g_v[(b*196)*1024 + c0];
    const bool rokm = (y0 > 0);        // row y0-1 valid
    const bool rokp = (y1 < 13);       // row y1+1 valid
    const int rm = (y0-1)*14336, r0 = y0*14336, r1 = y1*14336, rp = (y0+2)*14336;

    // window rows: 0 = y0-1, 1 = y0, 2 = y1, 3 = y1+1
    ull win[4][3];
    #pragma unroll
    for (int r = 0; r < 4; r++) win[r][0] = 0ULL;
    win[0][1] = rokm ? *(const ull*)&vbase[rm] : 0ULL;
    win[1][1] =        *(const ull*)&vbase[r0];
    win[2][1] =        *(const ull*)&vbase[r1];
    win[3][1] = rokp ? *(const ull*)&vbase[rp] : 0ULL;
    win[0][2] = rokm ? *(const ull*)&vbase[rm + 1024] : 0ULL;
    win[1][2] =        *(const ull*)&vbase[r0 + 1024];
    win[2][2] =        *(const ull*)&vbase[r1 + 1024];
    win[3][2] = rokp ? *(const ull*)&vbase[rp + 1024] : 0ULL;

    #pragma unroll
    for (int x = 0; x < 14; x++) {
        ull acc0 = 0ULL, acc1 = 0ULL;
        #pragma unroll
        for (int r = 0; r < 3; r++)
            #pragma unroll
            for (int j = 0; j < 3; j++) {
                acc0 = ffma2(win[r][j],   wt[r*3 + j], acc0);
                acc1 = ffma2(win[r+1][j], wt[r*3 + j], acc1);
            }
        float2 f0 = unpack2(acc0);
        float2 f1 = unpack2(acc1);
        float2 o0, o1;
        o0.x = fmaf(f0.x + bv2.x, sv2.x, tv2.x);
        o0.y = fmaf(f0.y + bv2.y, sv2.y, tv2.y);
        o1.x = fmaf(f1.x + bv2.x, sv2.x, tv2.x);
        o1.y = fmaf(f1.y + bv2.y, sv2.y, tv2.y);
        *reinterpret_cast<float2*>(&g_vl[(b*196 + y0*14 + x)*1024 + c0]) = o0;
        *reinterpret_cast<float2*>(&g_vl[(b*196 + y1*14 + x)*1024 + c0]) = o1;

        #pragma unroll
        for (int r = 0; r < 4; r++) { win[r][0] = win[r][1]; win[r][1] = win[r][2]; }
        if (x < 12) {
            int xo = (x+2)*1024;
            win[0][2] = rokm ? *(const ull*)&vbase[rm + xo] : 0ULL;
            win[1][2] =        *(const ull*)&vbase[r0 + xo];
            win[2][2] =        *(const ull*)&vbase[r1 + xo];
            win[3][2] = rokp ? *(const ull*)&vbase[rp + xo] : 0ULL;
        } else {
            win[0][2] = 0ULL; win[1][2] = 0ULL; win[2][2] = 0ULL; win[3][2] = 0ULL;
        }
    }
}

// ---------------- kernel 3: fused attention (512 thr, 7 q-rows, ping-pong) -
__global__ __launch_bounds__(512, 2) void attn_kernel(
    const float* __restrict__ th1, const float* __restrict__ bth1,
    const float* __restrict__ th2, const float* __restrict__ bth2,
    const int*   __restrict__ idxs)
{
    extern __shared__ __align__(16) float smem[];
    float* qs   = smem;             // 1792
    float* a3   = smem + 1792;      // 10976 raw logits / th2-mixed probs
    float* a2   = smem + 12768;     // 10976 th1-mixed logits / softmax probs
    float* abms = smem + 23744;     // 1568
    float* th1s = smem + 25312;     // 64 (pre-scaled)
    float* th2s = smem + 25376;     // 64
    float* bts  = smem + 25440;     // 16
    ull*   bt2u = reinterpret_cast<ull*>(smem + 25456);  // 8 ull

    const int tid = threadIdx.x;
    const int b  = blockIdx.y;
    const int n0 = blockIdx.x * 7;

    for (int idx = tid; idx < 1792; idx += 512)
        qs[idx] = g_q[(b*196 + n0 + (idx >> 8))*256 + (idx & 255)];
    for (int idx = tid; idx < 1568; idx += 512)
        abms[idx] = g_abm[idx];
    if (tid < 64) { th1s[tid] = th1[tid] * SCALE_; th2s[tid] = th2[tid]; }
    if (tid < 8)  { bts[tid] = bth1[tid]; bts[8 + tid] = bth2[tid];
                    bt2u[tid] = pack2(bth2[tid], bth2[tid]); }
    __syncthreads();

    // ---- phase 1: raw logits -> a3. item = (m, h), all 512 threads --------
    for (int it = tid; it < 1568; it += 512) {
        const int h = it / 196;
        const int m = it - h*196;
        // paired-K: base of pair cp = h*16, element (m, parity)
        const float* kb = &g_k[((b*128 + h*16)*196 + m)*2];
        ull s2[7];
        #pragma unroll
        for (int n = 0; n < 7; n++) s2[n] = 0ULL;
        #pragma unroll
        for (int c8 = 0; c8 < 8; c8++) {
            ull k01 = *reinterpret_cast<const ull*>(kb + c8*784);
            ull k23 = *reinterpret_cast<const ull*>(kb + c8*784 + 392);
            #pragma unroll
            for (int n = 0; n < 7; n++) {
                ulonglong2 q2 = *reinterpret_cast<const ulonglong2*>(&qs[n*256 + h*32 + c8*4]);
                s2[n] = ffma2(q2.x, k01, ffma2(q2.y, k23, s2[n]));
            }
        }
        #pragma unroll
        for (int n = 0; n < 7; n++) {
            float2 f = unpack2(s2[n]);
            a3[(n*8 + h)*196 + m] = f.x + f.y;
        }
    }
    __syncthreads();

    // ---- phase 1b: th1 mix + bias + ab : a3 -> a2 --------------------------
    {
        const int gp = tid >> 7;
        const int g0 = gp*2;
        ull wd0[8], wd1[8];
        #pragma unroll
        for (int h = 0; h < 8; h++) {
            float w0 = th1s[g0*8 + h], w1 = th1s[g0*8 + 8 + h];
            wd0[h] = pack2(w0, w0); wd1[h] = pack2(w1, w1);
        }
        const float bt0 = bts[g0], bt1 = bts[g0+1];
        const ull* a3u = reinterpret_cast<const ull*>(a3);
        ull* a2u = reinterpret_cast<ull*>(a2);
        for (int it = (tid & 127); it < 686; it += 128) {
            const int n = it / 98;
            const int pm = it - n*98;
            const int m0 = pm*2;
            int2 ixp = *reinterpret_cast<const int2*>(&idxs[(n0+n)*196 + m0]);
            ull t0 = pack2(bt0 + abms[g0*196 + ixp.x],     bt0 + abms[g0*196 + ixp.y]);
            ull t1 = pack2(bt1 + abms[(g0+1)*196 + ixp.x], bt1 + abms[(g0+1)*196 + ixp.y]);
            const ull* pb = a3u + n*784 + pm;
            #pragma unroll
            for (int h = 0; h < 8; h++) {
                ull p2 = pb[h*98];
                t0 = ffma2(p2, wd0[h], t0);
                t1 = ffma2(p2, wd1[h], t1);
            }
            a2u[(n*8 + g0)*98 + pm]     = t0;
            a2u[(n*8 + g0 + 1)*98 + pm] = t1;
        }
    }
    __syncthreads();

    // ---- phase 2: softmax on a2 (paired) -----------------------------------
    {
        const int w = tid >> 5, lane = tid & 31;
        for (int r = w; r < 56; r += 16) {
            ull* rowu = reinterpret_cast<ull*>(a2 + r*196);
            float mx = -1e30f;
            for (int i = lane; i < 98; i += 32) {
                float2 f = unpack2(rowu[i]);
                mx = fmaxf(mx, fmaxf(f.x, f.y));
            }
            #pragma unroll
            for (int off = 16; off > 0; off >>= 1)
                mx = fmaxf(mx, __shfl_xor_sync(0xffffffffu, mx, off));
            ull sm2 = 0ULL;
            for (int i = lane; i < 98; i += 32) {
                float2 f = unpack2(rowu[i]);
                f.x = __expf(f.x - mx); f.y = __expf(f.y - mx);
                ull e = pack2(f.x, f.y);
                rowu[i] = e;
                sm2 = fadd2(sm2, e);
            }
            float2 fs = unpack2(sm2);
            float sm = fs.x + fs.y;
            #pragma unroll
            for (int off = 16; off > 0; off >>= 1)
                sm += __shfl_xor_sync(0xffffffffu, sm, off);
            float inv = 1.f / sm;
            ull inv2 = pack2(inv, inv);
            for (int i = lane; i < 98; i += 32) rowu[i] = fmul2(rowu[i], inv2);
        }
    }
    __syncthreads();

    // ---- phase 3: th2 mix + bias : a2 -> a3 --------------------------------
    {
        const int gp = tid >> 7;
        const int g0 = gp*2;
        ull wd0[8], wd1[8];
        #pragma unroll
        for (int h = 0; h < 8; h++) {
            float w0 = th2s[g0*8 + h], w1 = th2s[g0*8 + 8 + h];
            wd0[h] = pack2(w0, w0); wd1[h] = pack2(w1, w1);
        }
        const ull bt0 = bt2u[g0], bt1 = bt2u[g0+1];
        const ull* a2u = reinterpret_cast<const ull*>(a2);
        ull* a3u = reinterpret_cast<ull*>(a3);
        for (int it = (tid & 127); it < 686; it += 128) {
            const int n = it / 98;
            const int pm = it - n*98;
            ull t0 = bt0, t1 = bt1;
            const ull* pb = a2u + n*784 + pm;
            #pragma unroll
            for (int h = 0; h < 8; h++) {
                ull p2 = pb[h*98];
                t0 = ffma2(p2, wd0[h], t0);
                t1 = ffma2(p2, wd1[h], t1);
            }
            a3u[(n*8 + g0)*98 + pm]     = t0;
            a3u[(n*8 + g0 + 1)*98 + pm] = t1;
        }
    }
    __syncthreads();

    // ---- phase 4: attn @ V + vl add + exact gelu ---------------------------
    // g_v2 delivers (c0_e, c0_o, c1_e, c1_o) per LDG.128 — zero packing MOVs.
    {
        const int head = tid >> 6;
        const int c0 = head*128 + (tid & 63)*2;
        ull accA[7], accB[7];
        #pragma unroll
        for (int n = 0; n < 7; n++) { accA[n] = 0ULL; accB[n] = 0ULL; }

        const ull* pbase = reinterpret_cast<const ull*>(a3) + head*98;
        const float* vb2 = &g_v2[((size_t)(b*98)*1024 + c0)*2];
        #pragma unroll 7
        for (int pm = 0; pm < 98; pm++) {
            ulonglong2 vv = *reinterpret_cast<const ulonglong2*>(vb2 + (size_t)pm*2048);
            #pragma unroll
            for (int n = 0; n < 7; n++) {
                ull p = pbase[n*784 + pm];
                accA[n] = ffma2(p, vv.x, accA[n]);
                accB[n] = ffma2(p, vv.y, accB[n]);
            }
        }
        #pragma unroll
        for (int n = 0; n < 7; n++) {
            int off = (b*196 + n0 + n)*1024 + c0;
            float2 vl2 = *reinterpret_cast<const float2*>(&g_vl[off]);
            float2 fA = unpack2(accA[n]);
            float2 fB = unpack2(accB[n]);
            float a0 = fA.x + fA.y + vl2.x;
            float a1 = fB.x + fB.y + vl2.y;
            float2 o2;
            o2.x = 0.5f * a0 * (1.f + erff(a0 * 0.7071067811865476f));
            o2.y = 0.5f * a1 * (1.f + erff(a1 * 0.7071067811865476f));
            *reinterpret_cast<float2*>(&g_ao[off]) = o2;
        }
    }
}

// ---------------- kernel 4: output projection GEMM -------------------------
__global__ __launch_bounds__(256, 2) void outproj_kernel(float* __restrict__ out)
{
    __shared__ __align__(16) float As[32][64];
    __shared__ __align__(16) float Bs[32][132];
    const int tid = threadIdx.x;
    const int tx = tid & 31, ty = tid >> 5;
    const int row0 = blockIdx.x * 128;
    const int o0 = blockIdx.y * 64;

    ull acc[4][4];
    #pragma unroll
    for (int i = 0; i < 4; i++)
        #pragma unroll
        for (int j = 0; j < 4; j++) acc[i][j] = 0ULL;

    for (int k0 = 0; k0 < 1024; k0 += 32) {
        #pragma unroll
        for (int i = 0; i < 8; i++) {
            int idx = tid + i*256;
            int kk = idx >> 6, o = idx & 63;
            As[kk][o] = g_wp[(k0+kk)*256 + o0 + o];
        }
        {
            int kk4 = (tid & 7) * 4;
            int rb = tid >> 3;
            #pragma unroll
            for (int i = 0; i < 4; i++) {
                int r = rb + i*32;
                float4 x4 = *reinterpret_cast<const float4*>(&g_ao[(row0+r)*1024 + k0 + kk4]);
                Bs[kk4+0][r] = x4.x; Bs[kk4+1][r] = x4.y;
                Bs[kk4+2][r] = x4.z; Bs[kk4+3][r] = x4.w;
            }
        }
        __syncthreads();
        #pragma unroll
        for (int kk = 0; kk < 32; kk++) {
            ulonglong2 a01 = *reinterpret_cast<const ulonglong2*>(&As[kk][ty*8]);
            ulonglong2 a23 = *reinterpret_cast<const ulonglong2*>(&As[kk][ty*8+4]);
            float4 b4 = *reinterpret_cast<const float4*>(&Bs[kk][tx*4]);
            ull bb0 = pack2(b4.x, b4.x), bb1 = pack2(b4.y, b4.y);
            ull bb2 = pack2(b4.z, b4.z), bb3 = pack2(b4.w, b4.w);
            acc[0][0] = ffma2(a01.x, bb0, acc[0][0]);
            acc[0][1] = ffma2(a01.x, bb1, acc[0][1]);
            acc[0][2] = ffma2(a01.x, bb2, acc[0][2]);
            acc[0][3] = ffma2(a01.x, bb3, acc[0][3]);
            acc[1][0] = ffma2(a01.y, bb0, acc[1][0]);
            acc[1][1] = ffma2(a01.y, bb1, acc[1][1]);
            acc[1][2] = ffma2(a01.y, bb2, acc[1][2]);
            acc[1][3] = ffma2(a01.y, bb3, acc[1][3]);
            acc[2][0] = ffma2(a23.x, bb0, acc[2][0]);
            acc[2][1] = ffma2(a23.x, bb1, acc[2][1]);
            acc[2][2] = ffma2(a23.x, bb2, acc[2][2]);
            acc[2][3] = ffma2(a23.x, bb3, acc[2][3]);
            acc[3][0] = ffma2(a23.y, bb0, acc[3][0]);
            acc[3][1] = ffma2(a23.y, bb1, acc[3][1]);
            acc[3][2] = ffma2(a23.y, bb2, acc[3][2]);
            acc[3][3] = ffma2(a23.y, bb3, acc[3][3]);
        }
        __syncthreads();
    }

    const int row = row0 + tx*4;
    const int b = row / 196, n = row - b*196;
    #pragma unroll
    for (int ip = 0; ip < 4; ip++) {
        float2 f0 = unpack2(acc[ip][0]);
        float2 f1 = unpack2(acc[ip][1]);
        float2 f2 = unpack2(acc[ip][2]);
        float2 f3 = unpack2(acc[ip][3]);
        int oA = o0 + ty*8 + ip*2;
        float biasA = g_bp[oA], biasB = g_bp[oA+1];
        float4 vA = make_float4(f0.x+biasA, f1.x+biasA, f2.x+biasA, f3.x+biasA);
        float4 vB = make_float4(f0.y+biasB, f1.y+biasB, f2.y+biasB, f3.y+biasB);
        *reinterpret_cast<float4*>(&out[b*50176 + oA*196 + n])     = vA;
        *reinterpret_cast<float4*>(&out[b*50176 + (oA+1)*196 + n]) = vB;
    }
}

// ---------------- launch ----------------------------------------------------
extern "C" void kernel_launch(void* const* d_in, const int* in_sizes, int n_in,
                              void* d_out, int out_size)
{
    const float* hs   = (const float*)d_in[0];
    const float* wq   = (const float*)d_in[1];
    const float* bq   = (const float*)d_in[2];
    const float* sq   = (const float*)d_in[3];
    const float* tq   = (const float*)d_in[4];
    const float* wk   = (const float*)d_in[5];
    const float* bk   = (const float*)d_in[6];
    const float* sk   = (const float*)d_in[7];
    const float* tk   = (const float*)d_in[8];
    const float* wv   = (const float*)d_in[9];
    const float* bv   = (const float*)d_in[10];
    const float* sv   = (const float*)d_in[11];
    const float* tv   = (const float*)d_in[12];
    const float* wvl  = (const float*)d_in[13];
    const float* bvl  = (const float*)d_in[14];
    const float* svl  = (const float*)d_in[15];
    const float* tvl  = (const float*)d_in[16];
    const float* th1  = (const float*)d_in[17];
    const float* bth1 = (const float*)d_in[18];
    const float* th2  = (const float*)d_in[19];
    const float* bth2 = (const float*)d_in[20];
    const float* wp   = (const float*)d_in[21];
    const float* bp   = (const float*)d_in[22];
    const float* sp   = (const float*)d_in[23];
    const float* tp   = (const float*)d_in[24];
    const float* ab   = (const float*)d_in[25];
    const int*   bidx = (const int*)d_in[26];

    cudaFuncSetAttribute(attn_kernel, cudaFuncAttributeMaxDynamicSharedMemorySize, 101888);

    const int pre_total = DIM_*QKV_ + DH_*DIM_ + QKV_ + 256 + H_*NOFF_;
    precompute_kernel<<<(pre_total + 255)/256, 256>>>(
        wq,bq,sq,tq, wk,bk,sk,tk, wv,bv,sv,tv, wp,bp,sp,tp, th1, ab);

    proj_kernel<<<dim3(392, 12), 256>>>(hs);
    dwconv_kernel<<<dim3(7, 128), 512>>>(wvl, bvl, svl, tvl);
    attn_kernel<<<dim3(28, 128), 512, 101888>>>(th1, bth1, th2, bth2, bidx);
    outproj_kernel<<<dim3(196, 4), 256>>>((float*)d_out);
}

// round 15
// speedup vs baseline: 1.6878x; 1.0665x over previous
#include <cuda_runtime.h>
#include <math.h>

// Problem constants
#define RES_ 14
#define N_ 196
#define B_ 128
#define DIM_ 256
#define H_ 8
#define KD_ 32
#define DV_ 128
#define DH_ 1024
#define NOFF_ 196
#define QKV_ 1536
#define SCALE_ 0.17677669529663687f

typedef unsigned long long ull;

// ---- packed fp32x2 helpers -------------------------------------------------
__device__ __forceinline__ ull ffma2(ull a, ull b, ull c) {
    ull d; asm("fma.rn.f32x2 %0, %1, %2, %3;" : "=l"(d) : "l"(a), "l"(b), "l"(c)); return d;
}
__device__ __forceinline__ ull fadd2(ull a, ull b) {
    ull d; asm("add.rn.f32x2 %0, %1, %2;" : "=l"(d) : "l"(a), "l"(b)); return d;
}
__device__ __forceinline__ ull fmul2(ull a, ull b) {
    ull d; asm("mul.rn.f32x2 %0, %1, %2;" : "=l"(d) : "l"(a), "l"(b)); return d;
}
__device__ __forceinline__ ull pack2(float lo, float hi) {
    ull d; asm("mov.b64 %0, {%1, %2};" : "=l"(d) : "f"(lo), "f"(hi)); return d;
}
__device__ __forceinline__ float2 unpack2(ull d) {
    float2 r; asm("mov.b64 {%0, %1}, %2;" : "=f"(r.x), "=f"(r.y) : "l"(d)); return r;
}

// ---------------- scratch (static device globals) --------------------------
__device__ __align__(16) float g_wall[DIM_*QKV_];
__device__ __align__(16) float g_ball[QKV_];
__device__ __align__(16) float g_wp[DH_*DIM_];
__device__ __align__(16) float g_bp[DIM_];
__device__ __align__(16) float g_abm[H_*NOFF_];
__device__ __align__(16) float g_q [B_*N_*256];     // (b,n,c)
// K paired layout: g_k[((b*128 + cp)*196 + m)*2 + par], cp=c/2, par=c&1
__device__ __align__(16) float g_k [B_*256*N_];
__device__ __align__(16) float g_v [B_*N_*DH_];     // (b,n,c) — for dwconv
// V interleaved: g_v2[((b*98+pm)*1024 + c0)*2 + {0..3}] = (c0_e, c0_o, c1_e, c1_o)
__device__ __align__(16) float g_v2[B_*N_*DH_];
__device__ __align__(16) float g_vl[B_*N_*DH_];
__device__ __align__(16) float g_ao[B_*N_*DH_];     // gelu(attn_out + vl)

// ---------------- kernel 0: fold scales / mix biases ------------------------
__global__ void precompute_kernel(
    const float* __restrict__ wq, const float* __restrict__ bq,
    const float* __restrict__ sq, const float* __restrict__ tq,
    const float* __restrict__ wk, const float* __restrict__ bk,
    const float* __restrict__ sk, const float* __restrict__ tk,
    const float* __restrict__ wv, const float* __restrict__ bv,
    const float* __restrict__ sv, const float* __restrict__ tv,
    const float* __restrict__ wp, const float* __restrict__ bp,
    const float* __restrict__ sp, const float* __restrict__ tp,
    const float* __restrict__ th1, const float* __restrict__ ab)
{
    int i = blockIdx.x * blockDim.x + threadIdx.x;
    if (i < DIM_*QKV_) {
        int c = i / QKV_, o = i % QKV_;
        float w;
        if (o < 256)       w = wq[c*256 + o]        * sq[o];
        else if (o < 512)  w = wk[c*256 + (o-256)]  * sk[o-256];
        else               w = wv[c*1024 + (o-512)] * sv[o-512];
        g_wall[i] = w;
        return;
    }
    int j = i - DIM_*QKV_;
    if (j < DH_*DIM_) {
        int c = j / 256, o = j % 256;
        g_wp[j] = wp[c*256 + o] * sp[o];
        return;
    }
    int l = j - DH_*DIM_;
    if (l < QKV_) {
        float v;
        if (l < 256)       v = bq[l]*sq[l] + tq[l];
        else if (l < 512)  v = bk[l-256]*sk[l-256] + tk[l-256];
        else               v = bv[l-512]*sv[l-512] + tv[l-512];
        g_ball[l] = v;
        return;
    }
    int m2 = l - QKV_;
    if (m2 < 256) { g_bp[m2] = bp[m2]*sp[m2] + tp[m2]; return; }
    int a = m2 - 256;
    if (a < H_*NOFF_) {
        int g = a / NOFF_, f = a % NOFF_;
        float s = 0.f;
        #pragma unroll
        for (int h = 0; h < 8; h++) s = fmaf(th1[g*8+h], ab[h*NOFF_ + f], s);
        g_abm[a] = s;
    }
}

// ---------------- kernel 1: fused QKV projection GEMM (128x128 tile) -------
// Thread tile: 16 lane-paired rows x 4 cols -> 4 MOVs amortized over 32 FFMA2.
__global__ __launch_bounds__(256, 2) void proj_kernel(const float* __restrict__ hs)
{
    __shared__ __align__(16) float Xs[32][128];   // [k][row]
    __shared__ __align__(16) float Ws[32][128];   // [k][o]
    const int tid = threadIdx.x;
    const int tx = tid & 31, ty = tid >> 5;
    const int rowBase = blockIdx.x * 128;
    const int bo = blockIdx.y * 128;

    // fill indexing: r/o constant per thread, kk = kb + 2i
    const int rfill = tid & 127;
    const int kb = tid >> 7;          // 0 or 1
    const int rowF = rowBase + rfill;
    const int bF = rowF / 196, nF = rowF - bF*196;
    const int xoff = bF*50176 + nF;

    ull acc[8][4];
    #pragma unroll
    for (int i = 0; i < 8; i++)
        #pragma unroll
        for (int j = 0; j < 4; j++) acc[i][j] = 0ULL;

    for (int k0 = 0; k0 < 256; k0 += 32) {
        #pragma unroll
        for (int i = 0; i < 16; i++) {
            int kk = kb + 2*i;
            Xs[kk][rfill] = hs[xoff + (k0 + kk)*196];
        }
        #pragma unroll
        for (int i = 0; i < 16; i++) {
            int kk = kb + 2*i;
            Ws[kk][rfill] = g_wall[(k0 + kk)*1536 + bo + rfill];
        }
        __syncthreads();
        #pragma unroll
        for (int kk = 0; kk < 32; kk++) {
            ulonglong2 xA = *reinterpret_cast<const ulonglong2*>(&Xs[kk][ty*16]);
            ulonglong2 xB = *reinterpret_cast<const ulonglong2*>(&Xs[kk][ty*16+4]);
            ulonglong2 xC = *reinterpret_cast<const ulonglong2*>(&Xs[kk][ty*16+8]);
            ulonglong2 xD = *reinterpret_cast<const ulonglong2*>(&Xs[kk][ty*16+12]);
            float4 b4 = *reinterpret_cast<const float4*>(&Ws[kk][tx*4]);
            ull bb0 = pack2(b4.x, b4.x), bb1 = pack2(b4.y, b4.y);
            ull bb2 = pack2(b4.z, b4.z), bb3 = pack2(b4.w, b4.w);
            acc[0][0] = ffma2(xA.x, bb0, acc[0][0]);
            acc[0][1] = ffma2(xA.x, bb1, acc[0][1]);
            acc[0][2] = ffma2(xA.x, bb2, acc[0][2]);
            acc[0][3] = ffma2(xA.x, bb3, acc[0][3]);
            acc[1][0] = ffma2(xA.y, bb0, acc[1][0]);
            acc[1][1] = ffma2(xA.y, bb1, acc[1][1]);
            acc[1][2] = ffma2(xA.y, bb2, acc[1][2]);
            acc[1][3] = ffma2(xA.y, bb3, acc[1][3]);
            acc[2][0] = ffma2(xB.x, bb0, acc[2][0]);
            acc[2][1] = ffma2(xB.x, bb1, acc[2][1]);
            acc[2][2] = ffma2(xB.x, bb2, acc[2][2]);
            acc[2][3] = ffma2(xB.x, bb3, acc[2][3]);
            acc[3][0] = ffma2(xB.y, bb0, acc[3][0]);
            acc[3][1] = ffma2(xB.y, bb1, acc[3][1]);
            acc[3][2] = ffma2(xB.y, bb2, acc[3][2]);
            acc[3][3] = ffma2(xB.y, bb3, acc[3][3]);
            acc[4][0] = ffma2(xC.x, bb0, acc[4][0]);
            acc[4][1] = ffma2(xC.x, bb1, acc[4][1]);
            acc[4][2] = ffma2(xC.x, bb2, acc[4][2]);
            acc[4][3] = ffma2(xC.x, bb3, acc[4][3]);
            acc[5][0] = ffma2(xC.y, bb0, acc[5][0]);
            acc[5][1] = ffma2(xC.y, bb1, acc[5][1]);
            acc[5][2] = ffma2(xC.y, bb2, acc[5][2]);
            acc[5][3] = ffma2(xC.y, bb3, acc[5][3]);
            acc[6][0] = ffma2(xD.x, bb0, acc[6][0]);
            acc[6][1] = ffma2(xD.x, bb1, acc[6][1]);
            acc[6][2] = ffma2(xD.x, bb2, acc[6][2]);
            acc[6][3] = ffma2(xD.x, bb3, acc[6][3]);
            acc[7][0] = ffma2(xD.y, bb0, acc[7][0]);
            acc[7][1] = ffma2(xD.y, bb1, acc[7][1]);
            acc[7][2] = ffma2(xD.y, bb2, acc[7][2]);
            acc[7][3] = ffma2(xD.y, bb3, acc[7][3]);
        }
        __syncthreads();
    }

    const int o4 = bo + tx*4;
    const float4 bia = *reinterpret_cast<const float4*>(&g_ball[o4]);
    #pragma unroll
    for (int ip = 0; ip < 8; ip++) {
        float2 f0 = unpack2(acc[ip][0]);
        float2 f1 = unpack2(acc[ip][1]);
        float2 f2 = unpack2(acc[ip][2]);
        float2 f3 = unpack2(acc[ip][3]);
        int r0 = rowBase + ty*16 + ip*2;    // always even
        float4 v0 = make_float4(f0.x+bia.x, f1.x+bia.y, f2.x+bia.z, f3.x+bia.w);
        float4 v1 = make_float4(f0.y+bia.x, f1.y+bia.y, f2.y+bia.z, f3.y+bia.w);
        if (bo < 256) {
            *reinterpret_cast<float4*>(&g_q[r0*256 + o4])     = v0;
            *reinterpret_cast<float4*>(&g_q[(r0+1)*256 + o4]) = v1;
        } else if (bo < 512) {
            const int cp0 = (o4 - 256) >> 1;   // even
            #pragma unroll
            for (int lane = 0; lane < 2; lane++) {
                int row = r0 + lane;
                int b = row / 196, n = row - b*196;
                float2 p0 = (lane == 0) ? make_float2(v0.x, v0.y) : make_float2(v1.x, v1.y);
                float2 p1 = (lane == 0) ? make_float2(v0.z, v0.w) : make_float2(v1.z, v1.w);
                *reinterpret_cast<float2*>(&g_k[((b*128 + cp0)*196 + n)*2])     = p0;
                *reinterpret_cast<float2*>(&g_k[((b*128 + cp0 + 1)*196 + n)*2]) = p1;
            }
        } else {
            *reinterpret_cast<float4*>(&g_v[r0*1024 + o4-512])     = v0;
            *reinterpret_cast<float4*>(&g_v[(r0+1)*1024 + o4-512]) = v1;
            int b = r0 / 196, n = r0 - b*196, pm = n >> 1;
            float4 qA = make_float4(v0.x, v1.x, v0.y, v1.y);
            float4 qB = make_float4(v0.z, v1.z, v0.w, v1.w);
            float* vb2 = &g_v2[(((size_t)b*98 + pm)*1024 + (o4-512))*2];
            *reinterpret_cast<float4*>(vb2)     = qA;
            *reinterpret_cast<float4*>(vb2 + 4) = qB;
        }
    }
}

// ---------------- kernel 2: depthwise 3x3 conv, 2 output rows per block ----
__global__ __launch_bounds__(512) void dwconv_kernel(
    const float* __restrict__ wvl, const float* __restrict__ bvl,
    const float* __restrict__ svl, const float* __restrict__ tvl)
{
    const int b = blockIdx.y;
    const int y0 = blockIdx.x * 2, y1 = y0 + 1;
    const int c0 = threadIdx.x * 2;

    ull wt[9];
    #pragma unroll
    for (int k = 0; k < 9; k++) wt[k] = pack2(wvl[c0*9 + k], wvl[c0*9 + 9 + k]);
    float2 bv2 = make_float2(bvl[c0], bvl[c0+1]);
    float2 sv2 = make_float2(svl[c0], svl[c0+1]);
    float2 tv2 = make_float2(tvl[c0], tvl[c0+1]);

    const float* vbase = &g_v[(b*196)*1024 + c0];
    const bool rokm = (y0 > 0);
    const bool rokp = (y1 < 13);
    const int rm = (y0-1)*14336, r0 = y0*14336, r1 = y1*14336, rp = (y0+2)*14336;

    ull win[4][3];
    #pragma unroll
    for (int r = 0; r < 4; r++) win[r][0] = 0ULL;
    win[0][1] = rokm ? *(const ull*)&vbase[rm] : 0ULL;
    win[1][1] =        *(const ull*)&vbase[r0];
    win[2][1] =        *(const ull*)&vbase[r1];
    win[3][1] = rokp ? *(const ull*)&vbase[rp] : 0ULL;
    win[0][2] = rokm ? *(const ull*)&vbase[rm + 1024] : 0ULL;
    win[1][2] =        *(const ull*)&vbase[r0 + 1024];
    win[2][2] =        *(const ull*)&vbase[r1 + 1024];
    win[3][2] = rokp ? *(const ull*)&vbase[rp + 1024] : 0ULL;

    #pragma unroll
    for (int x = 0; x < 14; x++) {
        ull acc0 = 0ULL, acc1 = 0ULL;
        #pragma unroll
        for (int r = 0; r < 3; r++)
            #pragma unroll
            for (int j = 0; j < 3; j++) {
                acc0 = ffma2(win[r][j],   wt[r*3 + j], acc0);
                acc1 = ffma2(win[r+1][j], wt[r*3 + j], acc1);
            }
        float2 f0 = unpack2(acc0);
        float2 f1 = unpack2(acc1);
        float2 o0, o1;
        o0.x = fmaf(f0.x + bv2.x, sv2.x, tv2.x);
        o0.y = fmaf(f0.y + bv2.y, sv2.y, tv2.y);
        o1.x = fmaf(f1.x + bv2.x, sv2.x, tv2.x);
        o1.y = fmaf(f1.y + bv2.y, sv2.y, tv2.y);
        *reinterpret_cast<float2*>(&g_vl[(b*196 + y0*14 + x)*1024 + c0]) = o0;
        *reinterpret_cast<float2*>(&g_vl[(b*196 + y1*14 + x)*1024 + c0]) = o1;

        #pragma unroll
        for (int r = 0; r < 4; r++) { win[r][0] = win[r][1]; win[r][1] = win[r][2]; }
        if (x < 12) {
            int xo = (x+2)*1024;
            win[0][2] = rokm ? *(const ull*)&vbase[rm + xo] : 0ULL;
            win[1][2] =        *(const ull*)&vbase[r0 + xo];
            win[2][2] =        *(const ull*)&vbase[r1 + xo];
            win[3][2] = rokp ? *(const ull*)&vbase[rp + xo] : 0ULL;
        } else {
            win[0][2] = 0ULL; win[1][2] = 0ULL; win[2][2] = 0ULL; win[3][2] = 0ULL;
        }
    }
}

// ---------------- kernel 3: fused attention (512 thr, 7 q-rows, ping-pong) -
__global__ __launch_bounds__(512, 2) void attn_kernel(
    const float* __restrict__ th1, const float* __restrict__ bth1,
    const float* __restrict__ th2, const float* __restrict__ bth2,
    const int*   __restrict__ idxs)
{
    extern __shared__ __align__(16) float smem[];
    float* qs   = smem;             // 1792
    float* a3   = smem + 1792;      // 10976 raw logits / th2-mixed probs
    float* a2   = smem + 12768;     // 10976 th1-mixed logits / softmax probs
    float* abms = smem + 23744;     // 1568
    float* th1s = smem + 25312;     // 64 (pre-scaled)
    float* th2s = smem + 25376;     // 64
    float* bts  = smem + 25440;     // 16
    ull*   bt2u = reinterpret_cast<ull*>(smem + 25456);  // 8 ull

    const int tid = threadIdx.x;
    const int b  = blockIdx.y;
    const int n0 = blockIdx.x * 7;

    for (int idx = tid; idx < 1792; idx += 512)
        qs[idx] = g_q[(b*196 + n0 + (idx >> 8))*256 + (idx & 255)];
    for (int idx = tid; idx < 1568; idx += 512)
        abms[idx] = g_abm[idx];
    if (tid < 64) { th1s[tid] = th1[tid] * SCALE_; th2s[tid] = th2[tid]; }
    if (tid < 8)  { bts[tid] = bth1[tid]; bts[8 + tid] = bth2[tid];
                    bt2u[tid] = pack2(bth2[tid], bth2[tid]); }
    __syncthreads();

    // ---- phase 1: raw logits -> a3. item = (m, h), all 512 threads --------
    for (int it = tid; it < 1568; it += 512) {
        const int h = it / 196;
        const int m = it - h*196;
        const float* kb = &g_k[((b*128 + h*16)*196 + m)*2];
        ull s2[7];
        #pragma unroll
        for (int n = 0; n < 7; n++) s2[n] = 0ULL;
        #pragma unroll
        for (int c8 = 0; c8 < 8; c8++) {
            ull k01 = *reinterpret_cast<const ull*>(kb + c8*784);
            ull k23 = *reinterpret_cast<const ull*>(kb + c8*784 + 392);
            #pragma unroll
            for (int n = 0; n < 7; n++) {
                ulonglong2 q2 = *reinterpret_cast<const ulonglong2*>(&qs[n*256 + h*32 + c8*4]);
                s2[n] = ffma2(q2.x, k01, ffma2(q2.y, k23, s2[n]));
            }
        }
        #pragma unroll
        for (int n = 0; n < 7; n++) {
            float2 f = unpack2(s2[n]);
            a3[(n*8 + h)*196 + m] = f.x + f.y;
        }
    }
    __syncthreads();

    // ---- phase 1b: th1 mix + bias + ab : a3 -> a2 --------------------------
    {
        const int gp = tid >> 7;
        const int g0 = gp*2;
        ull wd0[8], wd1[8];
        #pragma unroll
        for (int h = 0; h < 8; h++) {
            float w0 = th1s[g0*8 + h], w1 = th1s[g0*8 + 8 + h];
            wd0[h] = pack2(w0, w0); wd1[h] = pack2(w1, w1);
        }
        const float bt0 = bts[g0], bt1 = bts[g0+1];
        const ull* a3u = reinterpret_cast<const ull*>(a3);
        ull* a2u = reinterpret_cast<ull*>(a2);
        for (int it = (tid & 127); it < 686; it += 128) {
            const int n = it / 98;
            const int pm = it - n*98;
            const int m0 = pm*2;
            int2 ixp = *reinterpret_cast<const int2*>(&idxs[(n0+n)*196 + m0]);
            ull t0 = pack2(bt0 + abms[g0*196 + ixp.x],     bt0 + abms[g0*196 + ixp.y]);
            ull t1 = pack2(bt1 + abms[(g0+1)*196 + ixp.x], bt1 + abms[(g0+1)*196 + ixp.y]);
            const ull* pb = a3u + n*784 + pm;
            #pragma unroll
            for (int h = 0; h < 8; h++) {
                ull p2 = pb[h*98];
                t0 = ffma2(p2, wd0[h], t0);
                t1 = ffma2(p2, wd1[h], t1);
            }
            a2u[(n*8 + g0)*98 + pm]     = t0;
            a2u[(n*8 + g0 + 1)*98 + pm] = t1;
        }
    }
    __syncthreads();

    // ---- phase 2: softmax on a2 (paired) -----------------------------------
    {
        const int w = tid >> 5, lane = tid & 31;
        for (int r = w; r < 56; r += 16) {
            ull* rowu = reinterpret_cast<ull*>(a2 + r*196);
            float mx = -1e30f;
            for (int i = lane; i < 98; i += 32) {
                float2 f = unpack2(rowu[i]);
                mx = fmaxf(mx, fmaxf(f.x, f.y));
            }
            #pragma unroll
            for (int off = 16; off > 0; off >>= 1)
                mx = fmaxf(mx, __shfl_xor_sync(0xffffffffu, mx, off));
            ull sm2 = 0ULL;
            for (int i = lane; i < 98; i += 32) {
                float2 f = unpack2(rowu[i]);
                f.x = __expf(f.x - mx); f.y = __expf(f.y - mx);
                ull e = pack2(f.x, f.y);
                rowu[i] = e;
                sm2 = fadd2(sm2, e);
            }
            float2 fs = unpack2(sm2);
            float sm = fs.x + fs.y;
            #pragma unroll
            for (int off = 16; off > 0; off >>= 1)
                sm += __shfl_xor_sync(0xffffffffu, sm, off);
            float inv = 1.f / sm;
            ull inv2 = pack2(inv, inv);
            for (int i = lane; i < 98; i += 32) rowu[i] = fmul2(rowu[i], inv2);
        }
    }
    __syncthreads();

    // ---- phase 3: th2 mix + bias : a2 -> a3 --------------------------------
    {
        const int gp = tid >> 7;
        const int g0 = gp*2;
        ull wd0[8], wd1[8];
        #pragma unroll
        for (int h = 0; h < 8; h++) {
            float w0 = th2s[g0*8 + h], w1 = th2s[g0*8 + 8 + h];
            wd0[h] = pack2(w0, w0); wd1[h] = pack2(w1, w1);
        }
        const ull bt0 = bt2u[g0], bt1 = bt2u[g0+1];
        const ull* a2u = reinterpret_cast<const ull*>(a2);
        ull* a3u = reinterpret_cast<ull*>(a3);
        for (int it = (tid & 127); it < 686; it += 128) {
            const int n = it / 98;
            const int pm = it - n*98;
            ull t0 = bt0, t1 = bt1;
            const ull* pb = a2u + n*784 + pm;
            #pragma unroll
            for (int h = 0; h < 8; h++) {
                ull p2 = pb[h*98];
                t0 = ffma2(p2, wd0[h], t0);
                t1 = ffma2(p2, wd1[h], t1);
            }
            a3u[(n*8 + g0)*98 + pm]     = t0;
            a3u[(n*8 + g0 + 1)*98 + pm] = t1;
        }
    }
    __syncthreads();

    // ---- phase 4: attn @ V + vl add + exact gelu ---------------------------
    {
        const int head = tid >> 6;
        const int c0 = head*128 + (tid & 63)*2;
        ull accA[7], accB[7];
        #pragma unroll
        for (int n = 0; n < 7; n++) { accA[n] = 0ULL; accB[n] = 0ULL; }

        const ull* pbase = reinterpret_cast<const ull*>(a3) + head*98;
        const float* vb2 = &g_v2[((size_t)(b*98)*1024 + c0)*2];
        #pragma unroll 7
        for (int pm = 0; pm < 98; pm++) {
            ulonglong2 vv = *reinterpret_cast<const ulonglong2*>(vb2 + (size_t)pm*2048);
            #pragma unroll
            for (int n = 0; n < 7; n++) {
                ull p = pbase[n*784 + pm];
                accA[n] = ffma2(p, vv.x, accA[n]);
                accB[n] = ffma2(p, vv.y, accB[n]);
            }
        }
        #pragma unroll
        for (int n = 0; n < 7; n++) {
            int off = (b*196 + n0 + n)*1024 + c0;
            float2 vl2 = *reinterpret_cast<const float2*>(&g_vl[off]);
            float2 fA = unpack2(accA[n]);
            float2 fB = unpack2(accB[n]);
            float a0 = fA.x + fA.y + vl2.x;
            float a1 = fB.x + fB.y + vl2.y;
            float2 o2;
            o2.x = 0.5f * a0 * (1.f + erff(a0 * 0.7071067811865476f));
            o2.y = 0.5f * a1 * (1.f + erff(a1 * 0.7071067811865476f));
            *reinterpret_cast<float2*>(&g_ao[off]) = o2;
        }
    }
}

// ---------------- kernel 4: output projection GEMM (128o x 128row tile) ----
// Thread tile: 16 lane-paired o's x 4 rows.
__global__ __launch_bounds__(256, 2) void outproj_kernel(float* __restrict__ out)
{
    __shared__ __align__(16) float As[32][128];   // [k][o]
    __shared__ __align__(16) float Bs[32][132];   // [k][row], padded
    const int tid = threadIdx.x;
    const int tx = tid & 31, ty = tid >> 5;
    const int row0 = blockIdx.x * 128;
    const int o0 = blockIdx.y * 128;

    const int ofill = tid & 127;
    const int kb = tid >> 7;      // 0 or 1

    ull acc[8][4];
    #pragma unroll
    for (int i = 0; i < 8; i++)
        #pragma unroll
        for (int j = 0; j < 4; j++) acc[i][j] = 0ULL;

    for (int k0 = 0; k0 < 1024; k0 += 32) {
        #pragma unroll
        for (int i = 0; i < 16; i++) {
            int kk = kb + 2*i;
            As[kk][ofill] = g_wp[(k0 + kk)*256 + o0 + ofill];
        }
        {
            int kk4 = (tid & 7) * 4;
            int rb = tid >> 3;
            #pragma unroll
            for (int i = 0; i < 4; i++) {
                int r = rb + i*32;
                float4 x4 = *reinterpret_cast<const float4*>(&g_ao[(row0+r)*1024 + k0 + kk4]);
                Bs[kk4+0][r] = x4.x; Bs[kk4+1][r] = x4.y;
                Bs[kk4+2][r] = x4.z; Bs[kk4+3][r] = x4.w;
            }
        }
        __syncthreads();
        #pragma unroll
        for (int kk = 0; kk < 32; kk++) {
            ulonglong2 aA = *reinterpret_cast<const ulonglong2*>(&As[kk][ty*16]);
            ulonglong2 aB = *reinterpret_cast<const ulonglong2*>(&As[kk][ty*16+4]);
            ulonglong2 aC = *reinterpret_cast<const ulonglong2*>(&As[kk][ty*16+8]);
            ulonglong2 aD = *reinterpret_cast<const ulonglong2*>(&As[kk][ty*16+12]);
            float4 b4 = *reinterpret_cast<const float4*>(&Bs[kk][tx*4]);
            ull bb0 = pack2(b4.x, b4.x), bb1 = pack2(b4.y, b4.y);
            ull bb2 = pack2(b4.z, b4.z), bb3 = pack2(b4.w, b4.w);
            acc[0][0] = ffma2(aA.x, bb0, acc[0][0]);
            acc[0][1] = ffma2(aA.x, bb1, acc[0][1]);
            acc[0][2] = ffma2(aA.x, bb2, acc[0][2]);
            acc[0][3] = ffma2(aA.x, bb3, acc[0][3]);
            acc[1][0] = ffma2(aA.y, bb0, acc[1][0]);
            acc[1][1] = ffma2(aA.y, bb1, acc[1][1]);
            acc[1][2] = ffma2(aA.y, bb2, acc[1][2]);
            acc[1][3] = ffma2(aA.y, bb3, acc[1][3]);
            acc[2][0] = ffma2(aB.x, bb0, acc[2][0]);
            acc[2][1] = ffma2(aB.x, bb1, acc[2][1]);
            acc[2][2] = ffma2(aB.x, bb2, acc[2][2]);
            acc[2][3] = ffma2(aB.x, bb3, acc[2][3]);
            acc[3][0] = ffma2(aB.y, bb0, acc[3][0]);
            acc[3][1] = ffma2(aB.y, bb1, acc[3][1]);
            acc[3][2] = ffma2(aB.y, bb2, acc[3][2]);
            acc[3][3] = ffma2(aB.y, bb3, acc[3][3]);
            acc[4][0] = ffma2(aC.x, bb0, acc[4][0]);
            acc[4][1] = ffma2(aC.x, bb1, acc[4][1]);
            acc[4][2] = ffma2(aC.x, bb2, acc[4][2]);
            acc[4][3] = ffma2(aC.x, bb3, acc[4][3]);
            acc[5][0] = ffma2(aC.y, bb0, acc[5][0]);
            acc[5][1] = ffma2(aC.y, bb1, acc[5][1]);
            acc[5][2] = ffma2(aC.y, bb2, acc[5][2]);
            acc[5][3] = ffma2(aC.y, bb3, acc[5][3]);
            acc[6][0] = ffma2(aD.x, bb0, acc[6][0]);
            acc[6][1] = ffma2(aD.x, bb1, acc[6][1]);
            acc[6][2] = ffma2(aD.x, bb2, acc[6][2]);
            acc[6][3] = ffma2(aD.x, bb3, acc[6][3]);
            acc[7][0] = ffma2(aD.y, bb0, acc[7][0]);
            acc[7][1] = ffma2(aD.y, bb1, acc[7][1]);
            acc[7][2] = ffma2(aD.y, bb2, acc[7][2]);
            acc[7][3] = ffma2(aD.y, bb3, acc[7][3]);
        }
        __syncthreads();
    }

    const int row = row0 + tx*4;
    const int b = row / 196, n = row - b*196;
    #pragma unroll
    for (int ip = 0; ip < 8; ip++) {
        float2 f0 = unpack2(acc[ip][0]);
        float2 f1 = unpack2(acc[ip][1]);
        float2 f2 = unpack2(acc[ip][2]);
        float2 f3 = unpack2(acc[ip][3]);
        int oA = o0 + ty*16 + ip*2;
        float biasA = g_bp[oA], biasB = g_bp[oA+1];
        float4 vA = make_float4(f0.x+biasA, f1.x+biasA, f2.x+biasA, f3.x+biasA);
        float4 vB = make_float4(f0.y+biasB, f1.y+biasB, f2.y+biasB, f3.y+biasB);
        *reinterpret_cast<float4*>(&out[b*50176 + oA*196 + n])     = vA;
        *reinterpret_cast<float4*>(&out[b*50176 + (oA+1)*196 + n]) = vB;
    }
}

// ---------------- launch ----------------------------------------------------
extern "C" void kernel_launch(void* const* d_in, const int* in_sizes, int n_in,
                              void* d_out, int out_size)
{
    const float* hs   = (const float*)d_in[0];
    const float* wq   = (const float*)d_in[1];
    const float* bq   = (const float*)d_in[2];
    const float* sq   = (const float*)d_in[3];
    const float* tq   = (const float*)d_in[4];
    const float* wk   = (const float*)d_in[5];
    const float* bk   = (const float*)d_in[6];
    const float* sk   = (const float*)d_in[7];
    const float* tk   = (const float*)d_in[8];
    const float* wv   = (const float*)d_in[9];
    const float* bv   = (const float*)d_in[10];
    const float* sv   = (const float*)d_in[11];
    const float* tv   = (const float*)d_in[12];
    const float* wvl  = (const float*)d_in[13];
    const float* bvl  = (const float*)d_in[14];
    const float* svl  = (const float*)d_in[15];
    const float* tvl  = (const float*)d_in[16];
    const float* th1  = (const float*)d_in[17];
    const float* bth1 = (const float*)d_in[18];
    const float* th2  = (const float*)d_in[19];
    const float* bth2 = (const float*)d_in[20];
    const float* wp   = (const float*)d_in[21];
    const float* bp   = (const float*)d_in[22];
    const float* sp   = (const float*)d_in[23];
    const float* tp   = (const float*)d_in[24];
    const float* ab   = (const float*)d_in[25];
    const int*   bidx = (const int*)d_in[26];

    cudaFuncSetAttribute(attn_kernel, cudaFuncAttributeMaxDynamicSharedMemorySize, 101888);

    const int pre_total = DIM_*QKV_ + DH_*DIM_ + QKV_ + 256 + H_*NOFF_;
    precompute_kernel<<<(pre_total + 255)/256, 256>>>(
        wq,bq,sq,tq, wk,bk,sk,tk, wv,bv,sv,tv, wp,bp,sp,tp, th1, ab);

    proj_kernel<<<dim3(196, 12), 256>>>(hs);
    dwconv_kernel<<<dim3(7, 128), 512>>>(wvl, bvl, svl, tvl);
    attn_kernel<<<dim3(28, 128), 512, 101888>>>(th1, bth1, th2, bth2, bidx);
    outproj_kernel<<<dim3(196, 2), 256>>>((float*)d_out);
}

// round 16
// speedup vs baseline: 1.6934x; 1.0033x over previous
#include <cuda_runtime.h>
#include <math.h>

// Problem constants
#define RES_ 14
#define N_ 196
#define B_ 128
#define DIM_ 256
#define H_ 8
#define KD_ 32
#define DV_ 128
#define DH_ 1024
#define NOFF_ 196
#define QKV_ 1536
#define SCALE_ 0.17677669529663687f

typedef unsigned long long ull;

// ---- packed fp32x2 helpers -------------------------------------------------
__device__ __forceinline__ ull ffma2(ull a, ull b, ull c) {
    ull d; asm("fma.rn.f32x2 %0, %1, %2, %3;" : "=l"(d) : "l"(a), "l"(b), "l"(c)); return d;
}
__device__ __forceinline__ ull fadd2(ull a, ull b) {
    ull d; asm("add.rn.f32x2 %0, %1, %2;" : "=l"(d) : "l"(a), "l"(b)); return d;
}
__device__ __forceinline__ ull fmul2(ull a, ull b) {
    ull d; asm("mul.rn.f32x2 %0, %1, %2;" : "=l"(d) : "l"(a), "l"(b)); return d;
}
__device__ __forceinline__ ull pack2(float lo, float hi) {
    ull d; asm("mov.b64 %0, {%1, %2};" : "=l"(d) : "f"(lo), "f"(hi)); return d;
}
__device__ __forceinline__ float2 unpack2(ull d) {
    float2 r; asm("mov.b64 {%0, %1}, %2;" : "=f"(r.x), "=f"(r.y) : "l"(d)); return r;
}

// ---------------- scratch (static device globals) --------------------------
__device__ __align__(16) float g_wall[DIM_*QKV_];
__device__ __align__(16) float g_ball[QKV_];
__device__ __align__(16) float g_wp[DH_*DIM_];
__device__ __align__(16) float g_bp[DIM_];
__device__ __align__(16) float g_abm[H_*NOFF_];
__device__ __align__(16) float g_q [B_*N_*256];     // (b,n,c)
// K paired layout: g_k[((b*128 + cp)*196 + m)*2 + par], cp=c/2, par=c&1
__device__ __align__(16) float g_k [B_*256*N_];
__device__ __align__(16) float g_v [B_*N_*DH_];     // (b,n,c) — for dwconv
// V interleaved: g_v2[((b*98+pm)*1024 + c0)*2 + {0..3}] = (c0_e, c0_o, c1_e, c1_o)
__device__ __align__(16) float g_v2[B_*N_*DH_];
__device__ __align__(16) float g_vl[B_*N_*DH_];
__device__ __align__(16) float g_ao[B_*N_*DH_];     // gelu(attn_out + vl)

// ---------------- kernel 0: fold scales / mix biases ------------------------
__global__ void precompute_kernel(
    const float* __restrict__ wq, const float* __restrict__ bq,
    const float* __restrict__ sq, const float* __restrict__ tq,
    const float* __restrict__ wk, const float* __restrict__ bk,
    const float* __restrict__ sk, const float* __restrict__ tk,
    const float* __restrict__ wv, const float* __restrict__ bv,
    const float* __restrict__ sv, const float* __restrict__ tv,
    const float* __restrict__ wp, const float* __restrict__ bp,
    const float* __restrict__ sp, const float* __restrict__ tp,
    const float* __restrict__ th1, const float* __restrict__ ab)
{
    int i = blockIdx.x * blockDim.x + threadIdx.x;
    if (i < DIM_*QKV_) {
        int c = i / QKV_, o = i % QKV_;
        float w;
        if (o < 256)       w = wq[c*256 + o]        * sq[o];
        else if (o < 512)  w = wk[c*256 + (o-256)]  * sk[o-256];
        else               w = wv[c*1024 + (o-512)] * sv[o-512];
        g_wall[i] = w;
        return;
    }
    int j = i - DIM_*QKV_;
    if (j < DH_*DIM_) {
        int c = j / 256, o = j % 256;
        g_wp[j] = wp[c*256 + o] * sp[o];
        return;
    }
    int l = j - DH_*DIM_;
    if (l < QKV_) {
        float v;
        if (l < 256)       v = bq[l]*sq[l] + tq[l];
        else if (l < 512)  v = bk[l-256]*sk[l-256] + tk[l-256];
        else               v = bv[l-512]*sv[l-512] + tv[l-512];
        g_ball[l] = v;
        return;
    }
    int m2 = l - QKV_;
    if (m2 < 256) { g_bp[m2] = bp[m2]*sp[m2] + tp[m2]; return; }
    int a = m2 - 256;
    if (a < H_*NOFF_) {
        int g = a / NOFF_, f = a % NOFF_;
        float s = 0.f;
        #pragma unroll
        for (int h = 0; h < 8; h++) s = fmaf(th1[g*8+h], ab[h*NOFF_ + f], s);
        g_abm[a] = s;
    }
}

// ---------------- kernel 1: fused QKV projection GEMM (128x128 tile) -------
// Thread tile: 16 lane-paired rows x 4 cols -> 4 MOVs amortized over 32 FFMA2.
__global__ __launch_bounds__(256, 2) void proj_kernel(const float* __restrict__ hs)
{
    __shared__ __align__(16) float Xs[32][128];   // [k][row]
    __shared__ __align__(16) float Ws[32][128];   // [k][o]
    const int tid = threadIdx.x;
    const int tx = tid & 31, ty = tid >> 5;
    const int rowBase = blockIdx.x * 128;
    const int bo = blockIdx.y * 128;

    const int rfill = tid & 127;
    const int kb = tid >> 7;          // 0 or 1
    const int rowF = rowBase + rfill;
    const int bF = rowF / 196, nF = rowF - bF*196;
    const int xoff = bF*50176 + nF;

    ull acc[8][4];
    #pragma unroll
    for (int i = 0; i < 8; i++)
        #pragma unroll
        for (int j = 0; j < 4; j++) acc[i][j] = 0ULL;

    for (int k0 = 0; k0 < 256; k0 += 32) {
        #pragma unroll
        for (int i = 0; i < 16; i++) {
            int kk = kb + 2*i;
            Xs[kk][rfill] = hs[xoff + (k0 + kk)*196];
        }
        #pragma unroll
        for (int i = 0; i < 16; i++) {
            int kk = kb + 2*i;
            Ws[kk][rfill] = g_wall[(k0 + kk)*1536 + bo + rfill];
        }
        __syncthreads();
        #pragma unroll
        for (int kk = 0; kk < 32; kk++) {
            ulonglong2 xA = *reinterpret_cast<const ulonglong2*>(&Xs[kk][ty*16]);
            ulonglong2 xB = *reinterpret_cast<const ulonglong2*>(&Xs[kk][ty*16+4]);
            ulonglong2 xC = *reinterpret_cast<const ulonglong2*>(&Xs[kk][ty*16+8]);
            ulonglong2 xD = *reinterpret_cast<const ulonglong2*>(&Xs[kk][ty*16+12]);
            float4 b4 = *reinterpret_cast<const float4*>(&Ws[kk][tx*4]);
            ull bb0 = pack2(b4.x, b4.x), bb1 = pack2(b4.y, b4.y);
            ull bb2 = pack2(b4.z, b4.z), bb3 = pack2(b4.w, b4.w);
            acc[0][0] = ffma2(xA.x, bb0, acc[0][0]);
            acc[0][1] = ffma2(xA.x, bb1, acc[0][1]);
            acc[0][2] = ffma2(xA.x, bb2, acc[0][2]);
            acc[0][3] = ffma2(xA.x, bb3, acc[0][3]);
            acc[1][0] = ffma2(xA.y, bb0, acc[1][0]);
            acc[1][1] = ffma2(xA.y, bb1, acc[1][1]);
            acc[1][2] = ffma2(xA.y, bb2, acc[1][2]);
            acc[1][3] = ffma2(xA.y, bb3, acc[1][3]);
            acc[2][0] = ffma2(xB.x, bb0, acc[2][0]);
            acc[2][1] = ffma2(xB.x, bb1, acc[2][1]);
            acc[2][2] = ffma2(xB.x, bb2, acc[2][2]);
            acc[2][3] = ffma2(xB.x, bb3, acc[2][3]);
            acc[3][0] = ffma2(xB.y, bb0, acc[3][0]);
            acc[3][1] = ffma2(xB.y, bb1, acc[3][1]);
            acc[3][2] = ffma2(xB.y, bb2, acc[3][2]);
            acc[3][3] = ffma2(xB.y, bb3, acc[3][3]);
            acc[4][0] = ffma2(xC.x, bb0, acc[4][0]);
            acc[4][1] = ffma2(xC.x, bb1, acc[4][1]);
            acc[4][2] = ffma2(xC.x, bb2, acc[4][2]);
            acc[4][3] = ffma2(xC.x, bb3, acc[4][3]);
            acc[5][0] = ffma2(xC.y, bb0, acc[5][0]);
            acc[5][1] = ffma2(xC.y, bb1, acc[5][1]);
            acc[5][2] = ffma2(xC.y, bb2, acc[5][2]);
            acc[5][3] = ffma2(xC.y, bb3, acc[5][3]);
            acc[6][0] = ffma2(xD.x, bb0, acc[6][0]);
            acc[6][1] = ffma2(xD.x, bb1, acc[6][1]);
            acc[6][2] = ffma2(xD.x, bb2, acc[6][2]);
            acc[6][3] = ffma2(xD.x, bb3, acc[6][3]);
            acc[7][0] = ffma2(xD.y, bb0, acc[7][0]);
            acc[7][1] = ffma2(xD.y, bb1, acc[7][1]);
            acc[7][2] = ffma2(xD.y, bb2, acc[7][2]);
            acc[7][3] = ffma2(xD.y, bb3, acc[7][3]);
        }
        __syncthreads();
    }

    const int o4 = bo + tx*4;
    const float4 bia = *reinterpret_cast<const float4*>(&g_ball[o4]);
    #pragma unroll
    for (int ip = 0; ip < 8; ip++) {
        float2 f0 = unpack2(acc[ip][0]);
        float2 f1 = unpack2(acc[ip][1]);
        float2 f2 = unpack2(acc[ip][2]);
        float2 f3 = unpack2(acc[ip][3]);
        int r0 = rowBase + ty*16 + ip*2;    // always even
        float4 v0 = make_float4(f0.x+bia.x, f1.x+bia.y, f2.x+bia.z, f3.x+bia.w);
        float4 v1 = make_float4(f0.y+bia.x, f1.y+bia.y, f2.y+bia.z, f3.y+bia.w);
        if (bo < 256) {
            *reinterpret_cast<float4*>(&g_q[r0*256 + o4])     = v0;
            *reinterpret_cast<float4*>(&g_q[(r0+1)*256 + o4]) = v1;
        } else if (bo < 512) {
            const int cp0 = (o4 - 256) >> 1;   // even
            #pragma unroll
            for (int lane = 0; lane < 2; lane++) {
                int row = r0 + lane;
                int b = row / 196, n = row - b*196;
                float2 p0 = (lane == 0) ? make_float2(v0.x, v0.y) : make_float2(v1.x, v1.y);
                float2 p1 = (lane == 0) ? make_float2(v0.z, v0.w) : make_float2(v1.z, v1.w);
                *reinterpret_cast<float2*>(&g_k[((b*128 + cp0)*196 + n)*2])     = p0;
                *reinterpret_cast<float2*>(&g_k[((b*128 + cp0 + 1)*196 + n)*2]) = p1;
            }
        } else {
            *reinterpret_cast<float4*>(&g_v[r0*1024 + o4-512])     = v0;
            *reinterpret_cast<float4*>(&g_v[(r0+1)*1024 + o4-512]) = v1;
            int b = r0 / 196, n = r0 - b*196, pm = n >> 1;
            float4 qA = make_float4(v0.x, v1.x, v0.y, v1.y);
            float4 qB = make_float4(v0.z, v1.z, v0.w, v1.w);
            float* vb2 = &g_v2[(((size_t)b*98 + pm)*1024 + (o4-512))*2];
            *reinterpret_cast<float4*>(vb2)     = qA;
            *reinterpret_cast<float4*>(vb2 + 4) = qB;
        }
    }
}

// ---------------- kernel 2: depthwise 3x3 conv, 2 output rows per block ----
__global__ __launch_bounds__(512) void dwconv_kernel(
    const float* __restrict__ wvl, const float* __restrict__ bvl,
    const float* __restrict__ svl, const float* __restrict__ tvl)
{
    const int b = blockIdx.y;
    const int y0 = blockIdx.x * 2, y1 = y0 + 1;
    const int c0 = threadIdx.x * 2;

    ull wt[9];
    #pragma unroll
    for (int k = 0; k < 9; k++) wt[k] = pack2(wvl[c0*9 + k], wvl[c0*9 + 9 + k]);
    float2 bv2 = make_float2(bvl[c0], bvl[c0+1]);
    float2 sv2 = make_float2(svl[c0], svl[c0+1]);
    float2 tv2 = make_float2(tvl[c0], tvl[c0+1]);

    const float* vbase = &g_v[(b*196)*1024 + c0];
    const bool rokm = (y0 > 0);
    const bool rokp = (y1 < 13);
    const int rm = (y0-1)*14336, r0 = y0*14336, r1 = y1*14336, rp = (y0+2)*14336;

    ull win[4][3];
    #pragma unroll
    for (int r = 0; r < 4; r++) win[r][0] = 0ULL;
    win[0][1] = rokm ? *(const ull*)&vbase[rm] : 0ULL;
    win[1][1] =        *(const ull*)&vbase[r0];
    win[2][1] =        *(const ull*)&vbase[r1];
    win[3][1] = rokp ? *(const ull*)&vbase[rp] : 0ULL;
    win[0][2] = rokm ? *(const ull*)&vbase[rm + 1024] : 0ULL;
    win[1][2] =        *(const ull*)&vbase[r0 + 1024];
    win[2][2] =        *(const ull*)&vbase[r1 + 1024];
    win[3][2] = rokp ? *(const ull*)&vbase[rp + 1024] : 0ULL;

    #pragma unroll
    for (int x = 0; x < 14; x++) {
        ull acc0 = 0ULL, acc1 = 0ULL;
        #pragma unroll
        for (int r = 0; r < 3; r++)
            #pragma unroll
            for (int j = 0; j < 3; j++) {
                acc0 = ffma2(win[r][j],   wt[r*3 + j], acc0);
                acc1 = ffma2(win[r+1][j], wt[r*3 + j], acc1);
            }
        float2 f0 = unpack2(acc0);
        float2 f1 = unpack2(acc1);
        float2 o0, o1;
        o0.x = fmaf(f0.x + bv2.x, sv2.x, tv2.x);
        o0.y = fmaf(f0.y + bv2.y, sv2.y, tv2.y);
        o1.x = fmaf(f1.x + bv2.x, sv2.x, tv2.x);
        o1.y = fmaf(f1.y + bv2.y, sv2.y, tv2.y);
        *reinterpret_cast<float2*>(&g_vl[(b*196 + y0*14 + x)*1024 + c0]) = o0;
        *reinterpret_cast<float2*>(&g_vl[(b*196 + y1*14 + x)*1024 + c0]) = o1;

        #pragma unroll
        for (int r = 0; r < 4; r++) { win[r][0] = win[r][1]; win[r][1] = win[r][2]; }
        if (x < 12) {
            int xo = (x+2)*1024;
            win[0][2] = rokm ? *(const ull*)&vbase[rm + xo] : 0ULL;
            win[1][2] =        *(const ull*)&vbase[r0 + xo];
            win[2][2] =        *(const ull*)&vbase[r1 + xo];
            win[3][2] = rokp ? *(const ull*)&vbase[rp + xo] : 0ULL;
        } else {
            win[0][2] = 0ULL; win[1][2] = 0ULL; win[2][2] = 0ULL; win[3][2] = 0ULL;
        }
    }
}

// ---------------- kernel 3: fused attention (512 thr, 7 q-rows, ping-pong) -
__global__ __launch_bounds__(512, 2) void attn_kernel(
    const float* __restrict__ th1, const float* __restrict__ bth1,
    const float* __restrict__ th2, const float* __restrict__ bth2,
    const int*   __restrict__ idxs)
{
    extern __shared__ __align__(16) float smem[];
    float* qs   = smem;             // 1792
    float* a3   = smem + 1792;      // 10976 raw logits / th2-mixed probs
    float* a2   = smem + 12768;     // 10976 th1-mixed logits / softmax probs
    float* abms = smem + 23744;     // 1568
    float* th1s = smem + 25312;     // 64 (pre-scaled)
    float* th2s = smem + 25376;     // 64
    float* bts  = smem + 25440;     // 16
    ull*   bt2u = reinterpret_cast<ull*>(smem + 25456);  // 8 ull

    const int tid = threadIdx.x;
    const int b  = blockIdx.y;
    const int n0 = blockIdx.x * 7;

    for (int idx = tid; idx < 1792; idx += 512)
        qs[idx] = g_q[(b*196 + n0 + (idx >> 8))*256 + (idx & 255)];
    for (int idx = tid; idx < 1568; idx += 512)
        abms[idx] = g_abm[idx];
    if (tid < 64) { th1s[tid] = th1[tid] * SCALE_; th2s[tid] = th2[tid]; }
    if (tid < 8)  { bts[tid] = bth1[tid]; bts[8 + tid] = bth2[tid];
                    bt2u[tid] = pack2(bth2[tid], bth2[tid]); }
    __syncthreads();

    // ---- phase 1: raw logits -> a3. item = (m, h), all 512 threads --------
    for (int it = tid; it < 1568; it += 512) {
        const int h = it / 196;
        const int m = it - h*196;
        const float* kb = &g_k[((b*128 + h*16)*196 + m)*2];
        ull s2[7];
        #pragma unroll
        for (int n = 0; n < 7; n++) s2[n] = 0ULL;
        #pragma unroll
        for (int c8 = 0; c8 < 8; c8++) {
            ull k01 = *reinterpret_cast<const ull*>(kb + c8*784);
            ull k23 = *reinterpret_cast<const ull*>(kb + c8*784 + 392);
            #pragma unroll
            for (int n = 0; n < 7; n++) {
                ulonglong2 q2 = *reinterpret_cast<const ulonglong2*>(&qs[n*256 + h*32 + c8*4]);
                s2[n] = ffma2(q2.x, k01, ffma2(q2.y, k23, s2[n]));
            }
        }
        #pragma unroll
        for (int n = 0; n < 7; n++) {
            float2 f = unpack2(s2[n]);
            a3[(n*8 + h)*196 + m] = f.x + f.y;
        }
    }
    __syncthreads();

    // ---- phase 1b: th1 mix + bias + ab : a3 -> a2 --------------------------
    {
        const int gp = tid >> 7;
        const int g0 = gp*2;
        ull wd0[8], wd1[8];
        #pragma unroll
        for (int h = 0; h < 8; h++) {
            float w0 = th1s[g0*8 + h], w1 = th1s[g0*8 + 8 + h];
            wd0[h] = pack2(w0, w0); wd1[h] = pack2(w1, w1);
        }
        const float bt0 = bts[g0], bt1 = bts[g0+1];
        const ull* a3u = reinterpret_cast<const ull*>(a3);
        ull* a2u = reinterpret_cast<ull*>(a2);
        for (int it = (tid & 127); it < 686; it += 128) {
            const int n = it / 98;
            const int pm = it - n*98;
            const int m0 = pm*2;
            int2 ixp = *reinterpret_cast<const int2*>(&idxs[(n0+n)*196 + m0]);
            ull t0 = pack2(bt0 + abms[g0*196 + ixp.x],     bt0 + abms[g0*196 + ixp.y]);
            ull t1 = pack2(bt1 + abms[(g0+1)*196 + ixp.x], bt1 + abms[(g0+1)*196 + ixp.y]);
            const ull* pb = a3u + n*784 + pm;
            #pragma unroll
            for (int h = 0; h < 8; h++) {
                ull p2 = pb[h*98];
                t0 = ffma2(p2, wd0[h], t0);
                t1 = ffma2(p2, wd1[h], t1);
            }
            a2u[(n*8 + g0)*98 + pm]     = t0;
            a2u[(n*8 + g0 + 1)*98 + pm] = t1;
        }
    }
    __syncthreads();

    // ---- phase 2: softmax on a2 (paired) -----------------------------------
    {
        const int w = tid >> 5, lane = tid & 31;
        for (int r = w; r < 56; r += 16) {
            ull* rowu = reinterpret_cast<ull*>(a2 + r*196);
            float mx = -1e30f;
            for (int i = lane; i < 98; i += 32) {
                float2 f = unpack2(rowu[i]);
                mx = fmaxf(mx, fmaxf(f.x, f.y));
            }
            #pragma unroll
            for (int off = 16; off > 0; off >>= 1)
                mx = fmaxf(mx, __shfl_xor_sync(0xffffffffu, mx, off));
            ull sm2 = 0ULL;
            for (int i = lane; i < 98; i += 32) {
                float2 f = unpack2(rowu[i]);
                f.x = __expf(f.x - mx); f.y = __expf(f.y - mx);
                ull e = pack2(f.x, f.y);
                rowu[i] = e;
                sm2 = fadd2(sm2, e);
            }
            float2 fs = unpack2(sm2);
            float sm = fs.x + fs.y;
            #pragma unroll
            for (int off = 16; off > 0; off >>= 1)
                sm += __shfl_xor_sync(0xffffffffu, sm, off);
            float inv = 1.f / sm;
            ull inv2 = pack2(inv, inv);
            for (int i = lane; i < 98; i += 32) rowu[i] = fmul2(rowu[i], inv2);
        }
    }
    __syncthreads();

    // ---- phase 3: th2 mix + bias : a2 -> a3 --------------------------------
    {
        const int gp = tid >> 7;
        const int g0 = gp*2;
        ull wd0[8], wd1[8];
        #pragma unroll
        for (int h = 0; h < 8; h++) {
            float w0 = th2s[g0*8 + h], w1 = th2s[g0*8 + 8 + h];
            wd0[h] = pack2(w0, w0); wd1[h] = pack2(w1, w1);
        }
        const ull bt0 = bt2u[g0], bt1 = bt2u[g0+1];
        const ull* a2u = reinterpret_cast<const ull*>(a2);
        ull* a3u = reinterpret_cast<ull*>(a3);
        for (int it = (tid & 127); it < 686; it += 128) {
            const int n = it / 98;
            const int pm = it - n*98;
            ull t0 = bt0, t1 = bt1;
            const ull* pb = a2u + n*784 + pm;
            #pragma unroll
            for (int h = 0; h < 8; h++) {
                ull p2 = pb[h*98];
                t0 = ffma2(p2, wd0[h], t0);
                t1 = ffma2(p2, wd1[h], t1);
            }
            a3u[(n*8 + g0)*98 + pm]     = t0;
            a3u[(n*8 + g0 + 1)*98 + pm] = t1;
        }
    }
    __syncthreads();

    // ---- phase 4: attn @ V + vl add + exact gelu ---------------------------
    {
        const int head = tid >> 6;
        const int c0 = head*128 + (tid & 63)*2;
        ull accA[7], accB[7];
        #pragma unroll
        for (int n = 0; n < 7; n++) { accA[n] = 0ULL; accB[n] = 0ULL; }

        const ull* pbase = reinterpret_cast<const ull*>(a3) + head*98;
        const float* vb2 = &g_v2[((size_t)(b*98)*1024 + c0)*2];
        #pragma unroll 7
        for (int pm = 0; pm < 98; pm++) {
            ulonglong2 vv = *reinterpret_cast<const ulonglong2*>(vb2 + (size_t)pm*2048);
            #pragma unroll
            for (int n = 0; n < 7; n++) {
                ull p = pbase[n*784 + pm];
                accA[n] = ffma2(p, vv.x, accA[n]);
                accB[n] = ffma2(p, vv.y, accB[n]);
            }
        }
        #pragma unroll
        for (int n = 0; n < 7; n++) {
            int off = (b*196 + n0 + n)*1024 + c0;
            float2 vl2 = *reinterpret_cast<const float2*>(&g_vl[off]);
            float2 fA = unpack2(accA[n]);
            float2 fB = unpack2(accB[n]);
            float a0 = fA.x + fA.y + vl2.x;
            float a1 = fB.x + fB.y + vl2.y;
            float2 o2;
            o2.x = 0.5f * a0 * (1.f + erff(a0 * 0.7071067811865476f));
            o2.y = 0.5f * a1 * (1.f + erff(a1 * 0.7071067811865476f));
            *reinterpret_cast<float2*>(&g_ao[off]) = o2;
        }
    }
}

// ---------------- kernel 4: output projection GEMM (128o x 64row tile) -----
// 128-thread blocks for fine wave quantization (784 blocks, 4+ CTAs/SM).
// Thread tile unchanged: 16 lane-paired o's x 4 rows.
__global__ __launch_bounds__(128, 4) void outproj_kernel(float* __restrict__ out)
{
    __shared__ __align__(16) float As[32][128];   // [k][o]
    __shared__ __align__(16) float Bs[32][68];    // [k][row], padded
    const int tid = threadIdx.x;
    const int tx = tid & 15, ty = tid >> 4;       // 16 tx x 4 rows, 8 ty x 16 o
    const int row0 = blockIdx.x * 64;
    const int o0 = blockIdx.y * 128;

    ull acc[8][4];
    #pragma unroll
    for (int i = 0; i < 8; i++)
        #pragma unroll
        for (int j = 0; j < 4; j++) acc[i][j] = 0ULL;

    for (int k0 = 0; k0 < 1024; k0 += 32) {
        #pragma unroll
        for (int i = 0; i < 32; i++)
            As[i][tid] = g_wp[(k0 + i)*256 + o0 + tid];
        {
            int kk4 = (tid & 7) * 4;
            int rb = tid >> 3;        // 0..15
            #pragma unroll
            for (int i = 0; i < 4; i++) {
                int r = rb + i*16;
                float4 x4 = *reinterpret_cast<const float4*>(&g_ao[(row0+r)*1024 + k0 + kk4]);
                Bs[kk4+0][r] = x4.x; Bs[kk4+1][r] = x4.y;
                Bs[kk4+2][r] = x4.z; Bs[kk4+3][r] = x4.w;
            }
        }
        __syncthreads();
        #pragma unroll
        for (int kk = 0; kk < 32; kk++) {
            ulonglong2 aA = *reinterpret_cast<const ulonglong2*>(&As[kk][ty*16]);
            ulonglong2 aB = *reinterpret_cast<const ulonglong2*>(&As[kk][ty*16+4]);
            ulonglong2 aC = *reinterpret_cast<const ulonglong2*>(&As[kk][ty*16+8]);
            ulonglong2 aD = *reinterpret_cast<const ulonglong2*>(&As[kk][ty*16+12]);
            float4 b4 = *reinterpret_cast<const float4*>(&Bs[kk][tx*4]);
            ull bb0 = pack2(b4.x, b4.x), bb1 = pack2(b4.y, b4.y);
            ull bb2 = pack2(b4.z, b4.z), bb3 = pack2(b4.w, b4.w);
            acc[0][0] = ffma2(aA.x, bb0, acc[0][0]);
            acc[0][1] = ffma2(aA.x, bb1, acc[0][1]);
            acc[0][2] = ffma2(aA.x, bb2, acc[0][2]);
            acc[0][3] = ffma2(aA.x, bb3, acc[0][3]);
            acc[1][0] = ffma2(aA.y, bb0, acc[1][0]);
            acc[1][1] = ffma2(aA.y, bb1, acc[1][1]);
            acc[1][2] = ffma2(aA.y, bb2, acc[1][2]);
            acc[1][3] = ffma2(aA.y, bb3, acc[1][3]);
            acc[2][0] = ffma2(aB.x, bb0, acc[2][0]);
            acc[2][1] = ffma2(aB.x, bb1, acc[2][1]);
            acc[2][2] = ffma2(aB.x, bb2, acc[2][2]);
            acc[2][3] = ffma2(aB.x, bb3, acc[2][3]);
            acc[3][0] = ffma2(aB.y, bb0, acc[3][0]);
            acc[3][1] = ffma2(aB.y, bb1, acc[3][1]);
            acc[3][2] = ffma2(aB.y, bb2, acc[3][2]);
            acc[3][3] = ffma2(aB.y, bb3, acc[3][3]);
            acc[4][0] = ffma2(aC.x, bb0, acc[4][0]);
            acc[4][1] = ffma2(aC.x, bb1, acc[4][1]);
            acc[4][2] = ffma2(aC.x, bb2, acc[4][2]);
            acc[4][3] = ffma2(aC.x, bb3, acc[4][3]);
            acc[5][0] = ffma2(aC.y, bb0, acc[5][0]);
            acc[5][1] = ffma2(aC.y, bb1, acc[5][1]);
            acc[5][2] = ffma2(aC.y, bb2, acc[5][2]);
            acc[5][3] = ffma2(aC.y, bb3, acc[5][3]);
            acc[6][0] = ffma2(aD.x, bb0, acc[6][0]);
            acc[6][1] = ffma2(aD.x, bb1, acc[6][1]);
            acc[6][2] = ffma2(aD.x, bb2, acc[6][2]);
            acc[6][3] = ffma2(aD.x, bb3, acc[6][3]);
            acc[7][0] = ffma2(aD.y, bb0, acc[7][0]);
            acc[7][1] = ffma2(aD.y, bb1, acc[7][1]);
            acc[7][2] = ffma2(aD.y, bb2, acc[7][2]);
            acc[7][3] = ffma2(aD.y, bb3, acc[7][3]);
        }
        __syncthreads();
    }

    const int row = row0 + tx*4;
    const int b = row / 196, n = row - b*196;
    #pragma unroll
    for (int ip = 0; ip < 8; ip++) {
        float2 f0 = unpack2(acc[ip][0]);
        float2 f1 = unpack2(acc[ip][1]);
        float2 f2 = unpack2(acc[ip][2]);
        float2 f3 = unpack2(acc[ip][3]);
        int oA = o0 + ty*16 + ip*2;
        float biasA = g_bp[oA], biasB = g_bp[oA+1];
        float4 vA = make_float4(f0.x+biasA, f1.x+biasA, f2.x+biasA, f3.x+biasA);
        float4 vB = make_float4(f0.y+biasB, f1.y+biasB, f2.y+biasB, f3.y+biasB);
        *reinterpret_cast<float4*>(&out[b*50176 + oA*196 + n])     = vA;
        *reinterpret_cast<float4*>(&out[b*50176 + (oA+1)*196 + n]) = vB;
    }
}

// ---------------- launch ----------------------------------------------------
extern "C" void kernel_launch(void* const* d_in, const int* in_sizes, int n_in,
                              void* d_out, int out_size)
{
    const float* hs   = (const float*)d_in[0];
    const float* wq   = (const float*)d_in[1];
    const float* bq   = (const float*)d_in[2];
    const float* sq   = (const float*)d_in[3];
    const float* tq   = (const float*)d_in[4];
    const float* wk   = (const float*)d_in[5];
    const float* bk   = (const float*)d_in[6];
    const float* sk   = (const float*)d_in[7];
    const float* tk   = (const float*)d_in[8];
    const float* wv   = (const float*)d_in[9];
    const float* bv   = (const float*)d_in[10];
    const float* sv   = (const float*)d_in[11];
    const float* tv   = (const float*)d_in[12];
    const float* wvl  = (const float*)d_in[13];
    const float* bvl  = (const float*)d_in[14];
    const float* svl  = (const float*)d_in[15];
    const float* tvl  = (const float*)d_in[16];
    const float* th1  = (const float*)d_in[17];
    const float* bth1 = (const float*)d_in[18];
    const float* th2  = (const float*)d_in[19];
    const float* bth2 = (const float*)d_in[20];
    const float* wp   = (const float*)d_in[21];
    const float* bp   = (const float*)d_in[22];
    const float* sp   = (const float*)d_in[23];
    const float* tp   = (const float*)d_in[24];
    const float* ab   = (const float*)d_in[25];
    const int*   bidx = (const int*)d_in[26];

    cudaFuncSetAttribute(attn_kernel, cudaFuncAttributeMaxDynamicSharedMemorySize, 101888);

    const int pre_total = DIM_*QKV_ + DH_*DIM_ + QKV_ + 256 + H_*NOFF_;
    precompute_kernel<<<(pre_total + 255)/256, 256>>>(
        wq,bq,sq,tq, wk,bk,sk,tk, wv,bv,sv,tv, wp,bp,sp,tp, th1, ab);

    proj_kernel<<<dim3(196, 12), 256>>>(hs);
    dwconv_kernel<<<dim3(7, 128), 512>>>(wvl, bvl, svl, tvl);
    attn_kernel<<<dim3(28, 128), 512, 101888>>>(th1, bth1, th2, bth2, bidx);
    outproj_kernel<<<dim3(392, 2), 128>>>((float*)d_out);
}